// round 1
// baseline (speedup 1.0000x reference)
#include <cuda_runtime.h>
#include <math.h>

// Problem constants
#define BB 8
#define NN 256
#define DD 384
#define LL 6
#define HH 8
#define FFD 1536
#define TT 4
#define DH 48
#define NM1 517
#define SS 1034
#define MM (BB*SS)   // 8272

// ---------------- scratch (static device globals; no allocation) ----------------
__device__ float g_SRC [BB*SS*DD];
__device__ float g_COORD[BB*SS*3];
__device__ float g_Q   [BB*SS*DD];
__device__ float g_K   [BB*SS*DD];
__device__ float g_V   [BB*SS*DD];
__device__ float g_ATT [BB*SS*DD];
__device__ float g_PROJ[BB*SS*DD];
__device__ float g_FF  [BB*SS*FFD];

// ---------------- input assembly ----------------
__global__ void build_src_kernel(const float* __restrict__ hand_t, const float* __restrict__ head_t,
                                 const float* __restrict__ hand_m1, const float* __restrict__ head_m1,
                                 const float* __restrict__ state_t, const float* __restrict__ state_m1,
                                 const float* __restrict__ tok_m1, const float* __restrict__ tok_t)
{
    for (int idx = blockIdx.x*blockDim.x + threadIdx.x; idx < BB*SS*DD; idx += gridDim.x*blockDim.x) {
        int d = idx % DD;
        int s = (idx / DD) % SS;
        int b = idx / (DD*SS);
        float v;
        if      (s == 0)    v = state_m1[b*DD + d];
        else if (s < 257)   v = hand_m1[((b*NN)+(s-1  ))*DD + d];
        else if (s < 513)   v = head_m1[((b*NN)+(s-257))*DD + d];
        else if (s < 517)   v = tok_m1[(s-513)*DD + d];
        else if (s == 517)  v = state_t[b*DD + d];
        else if (s < 774)   v = hand_t[((b*NN)+(s-518))*DD + d];
        else if (s < 1030)  v = head_t[((b*NN)+(s-774))*DD + d];
        else                v = tok_t[(s-1030)*DD + d];
        g_SRC[idx] = v;
    }
}

__global__ void build_coord_kernel(const float* __restrict__ c_hand_t, const float* __restrict__ c_head_t,
                                   const float* __restrict__ c_hand_m1, const float* __restrict__ c_head_m1,
                                   const float* __restrict__ tr_t, const float* __restrict__ tr_m1)
{
    for (int idx = blockIdx.x*blockDim.x + threadIdx.x; idx < BB*SS*3; idx += gridDim.x*blockDim.x) {
        int cdim = idx % 3;
        int s = (idx/3) % SS;
        int b = idx / (3*SS);
        float v;
        if      (s == 0)    v = tr_m1[b*3+cdim];
        else if (s < 257)   v = c_hand_m1[((b*NN)+(s-1  ))*3 + cdim];
        else if (s < 513)   v = c_head_m1[((b*NN)+(s-257))*3 + cdim];
        else if (s < 517)   v = tr_m1[b*3+cdim];
        else if (s == 517)  v = tr_t[b*3+cdim];
        else if (s < 774)   v = c_hand_t[((b*NN)+(s-518))*3 + cdim];
        else if (s < 1030)  v = c_head_t[((b*NN)+(s-774))*3 + cdim];
        else                v = tr_t[b*3+cdim];
        g_COORD[idx] = v;
    }
}

// ---------------- generic fp32 SGEMM:  C[m,n] = sum_k A[m,k]*W[n,k] + bias[n]  (opt. GELU) ----
// A: [M,Kd] row-major, W: [Ncols,Kd] row-major. Ncols % 128 == 0, Kd % 8 == 0 (guaranteed here).
template<bool DO_GELU>
__global__ void __launch_bounds__(256) sgemm_nt_kernel(int M, int Ncols, int Kd,
    const float* __restrict__ A, const float* __restrict__ W,
    const float* __restrict__ bias, float* __restrict__ C)
{
    __shared__ float As[8][128];
    __shared__ float Ws[8][128];
    const int tid  = threadIdx.x;
    const int m0   = blockIdx.x * 128;
    const int n0   = blockIdx.y * 128;
    const int trow = tid >> 4;          // 0..15
    const int tcol = tid & 15;          // 0..15
    const int ldRow = tid >> 1;         // 0..127
    const int ldK   = (tid & 1) * 4;    // 0 or 4

    float acc[8][8];
    #pragma unroll
    for (int i = 0; i < 8; i++)
        #pragma unroll
        for (int j = 0; j < 8; j++) acc[i][j] = 0.f;

    const bool aValid = (m0 + ldRow) < M;
    const float* Ap = A + (size_t)(m0 + ldRow) * Kd + ldK;
    const float* Wp = W + (size_t)(n0 + ldRow) * Kd + ldK;

    for (int k0 = 0; k0 < Kd; k0 += 8) {
        float4 av = aValid ? *(const float4*)(Ap + k0) : make_float4(0.f,0.f,0.f,0.f);
        float4 wv = *(const float4*)(Wp + k0);
        __syncthreads();
        As[ldK+0][ldRow]=av.x; As[ldK+1][ldRow]=av.y; As[ldK+2][ldRow]=av.z; As[ldK+3][ldRow]=av.w;
        Ws[ldK+0][ldRow]=wv.x; Ws[ldK+1][ldRow]=wv.y; Ws[ldK+2][ldRow]=wv.z; Ws[ldK+3][ldRow]=wv.w;
        __syncthreads();
        #pragma unroll
        for (int kk = 0; kk < 8; kk++) {
            float a[8], w[8];
            *(float4*)&a[0] = *(const float4*)&As[kk][trow*8];
            *(float4*)&a[4] = *(const float4*)&As[kk][trow*8+4];
            *(float4*)&w[0] = *(const float4*)&Ws[kk][tcol*8];
            *(float4*)&w[4] = *(const float4*)&Ws[kk][tcol*8+4];
            #pragma unroll
            for (int i = 0; i < 8; i++)
                #pragma unroll
                for (int j = 0; j < 8; j++)
                    acc[i][j] += a[i]*w[j];
        }
    }

    #pragma unroll
    for (int i = 0; i < 8; i++) {
        int m = m0 + trow*8 + i;
        if (m >= M) continue;
        #pragma unroll
        for (int jj = 0; jj < 8; jj += 4) {
            float4 o;
            {
                float v0 = acc[i][jj+0] + bias[n0 + tcol*8 + jj + 0];
                float v1 = acc[i][jj+1] + bias[n0 + tcol*8 + jj + 1];
                float v2 = acc[i][jj+2] + bias[n0 + tcol*8 + jj + 2];
                float v3 = acc[i][jj+3] + bias[n0 + tcol*8 + jj + 3];
                if (DO_GELU) {
                    v0 = 0.5f*v0*(1.0f+erff(v0*0.7071067811865475f));
                    v1 = 0.5f*v1*(1.0f+erff(v1*0.7071067811865475f));
                    v2 = 0.5f*v2*(1.0f+erff(v2*0.7071067811865475f));
                    v3 = 0.5f*v3*(1.0f+erff(v3*0.7071067811865475f));
                }
                o.x=v0; o.y=v1; o.z=v2; o.w=v3;
            }
            *(float4*)&C[(size_t)m*Ncols + n0 + tcol*8 + jj] = o;
        }
    }
}

// ---------------- rotary PE (in-place on g_Q, g_K) ----------------
__global__ void rope_kernel()
{
    int idx = blockIdx.x*blockDim.x + threadIdx.x;
    if (idx >= BB*SS*HH) return;
    int h = idx % HH;
    int s = (idx/HH) % SS;
    int b = idx / (HH*SS);
    size_t base = ((size_t)(b*SS + s))*DD + h*DH;

    float invf[8];
    #pragma unroll
    for (int j = 0; j < 8; j++)
        invf[j] = exp2f(-1.6609640474436813f * (float)j);  // 10000^(-j/8)

    #pragma unroll
    for (int a = 0; a < 3; a++) {
        float co = g_COORD[(b*SS+s)*3 + a];
        #pragma unroll
        for (int j = 0; j < 8; j++) {
            float ang = co * invf[j];
            float cs = cosf(ang), sn = sinf(ang);
            size_t i1 = base + a*16 + j, i2 = i1 + 8;
            float q1 = g_Q[i1], q2 = g_Q[i2];
            g_Q[i1] = q1*cs - q2*sn;  g_Q[i2] = q1*sn + q2*cs;
            float k1 = g_K[i1], k2 = g_K[i2];
            g_K[i1] = k1*cs - k2*sn;  g_K[i2] = k1*sn + k2*cs;
        }
    }
}

// ---------------- flash attention ----------------
// grid: (17 q-tiles of 64, B*H).  block: 256 = 64 rows x 4 key-lanes.
__global__ void __launch_bounds__(256) attn_kernel(const float* __restrict__ Q,
                                                   const float* __restrict__ K,
                                                   const float* __restrict__ V,
                                                   float* __restrict__ O)
{
    const int bh = blockIdx.y;
    const int b = bh >> 3, h = bh & 7;
    const int q0 = blockIdx.x * 64;
    const int tid = threadIdx.x;
    const int r = tid >> 2, c = tid & 3;
    const int qrow = q0 + r;

    __shared__ float Ks[64*52];
    __shared__ float Vs[64*52];

    const float scale = 0.14433756729740643f; // 1/sqrt(48)
    float qreg[48];
    {
        int qr = qrow < SS ? qrow : SS-1;
        const float* qp = Q + ((size_t)(b*SS + qr))*DD + h*DH;
        #pragma unroll
        for (int i = 0; i < 12; i++) {
            float4 t = *(const float4*)(qp + i*4);
            qreg[i*4+0]=t.x*scale; qreg[i*4+1]=t.y*scale; qreg[i*4+2]=t.z*scale; qreg[i*4+3]=t.w*scale;
        }
    }

    float m_i = -INFINITY, l_i = 0.f;
    float acc[48];
    #pragma unroll
    for (int i = 0; i < 48; i++) acc[i] = 0.f;

    const size_t baseBK = (size_t)b*SS*DD + h*DH;

    for (int kt = 0; kt < 17; kt++) {
        int k0 = kt * 64;
        // block-uniform skip of fully masked tiles (m1 queries can't see t keys)
        if ((q0 + 63 < NM1) && (k0 >= NM1)) continue;

        __syncthreads();
        #pragma unroll
        for (int it = 0; it < 3; it++) {
            int idx = tid + it*256;
            int row = idx / 12, f4 = (idx % 12)*4;
            int kg = k0 + row;
            float4 kv, vv;
            if (kg < SS) {
                kv = *(const float4*)(K + baseBK + (size_t)kg*DD + f4);
                vv = *(const float4*)(V + baseBK + (size_t)kg*DD + f4);
            } else {
                kv = make_float4(0.f,0.f,0.f,0.f); vv = kv;
            }
            *(float4*)&Ks[row*52 + f4] = kv;
            *(float4*)&Vs[row*52 + f4] = vv;
        }
        __syncthreads();

        float p[16];
        float tmax = -INFINITY;
        #pragma unroll
        for (int kk = 0; kk < 16; kk++) {
            int kl = c + 4*kk;
            int kg = k0 + kl;
            const float* kp = &Ks[kl*52];
            float dot = 0.f;
            #pragma unroll
            for (int i = 0; i < 48; i++) dot += qreg[i]*kp[i];
            bool masked = (kg >= SS) || (qrow < NM1 && kg >= NM1);
            p[kk] = masked ? -INFINITY : dot;
            tmax = fmaxf(tmax, p[kk]);
        }
        tmax = fmaxf(tmax, __shfl_xor_sync(0xffffffffu, tmax, 1));
        tmax = fmaxf(tmax, __shfl_xor_sync(0xffffffffu, tmax, 2));
        float newm = fmaxf(m_i, tmax);
        float factor = __expf(m_i - newm);   // m_i=-inf first time -> 0
        m_i = newm;

        float psum = 0.f;
        #pragma unroll
        for (int kk = 0; kk < 16; kk++) { p[kk] = __expf(p[kk] - m_i); psum += p[kk]; }
        psum += __shfl_xor_sync(0xffffffffu, psum, 1);
        psum += __shfl_xor_sync(0xffffffffu, psum, 2);
        l_i = l_i * factor + psum;

        #pragma unroll
        for (int i = 0; i < 48; i++) acc[i] *= factor;

        #pragma unroll
        for (int kk = 0; kk < 16; kk++) {
            float pv = p[kk];
            if (pv > 0.f) {
                const float* vp = &Vs[(c + 4*kk)*52];
                #pragma unroll
                for (int i = 0; i < 48; i++) acc[i] += pv*vp[i];
            }
        }
    }

    // reduce partial outputs across the 4 key-lanes of each row
    #pragma unroll
    for (int i = 0; i < 48; i++) {
        float v = acc[i];
        v += __shfl_xor_sync(0xffffffffu, v, 1);
        v += __shfl_xor_sync(0xffffffffu, v, 2);
        acc[i] = v;
    }
    if (c == 0 && qrow < SS) {
        float inv_l = 1.f / l_i;
        float* op = O + ((size_t)(b*SS + qrow))*DD + h*DH;
        #pragma unroll
        for (int i = 0; i < 12; i++) {
            float4 o;
            o.x = acc[i*4+0]*inv_l; o.y = acc[i*4+1]*inv_l;
            o.z = acc[i*4+2]*inv_l; o.w = acc[i*4+3]*inv_l;
            *(float4*)(op + i*4) = o;
        }
    }
}

// ---------------- residual add + layernorm (in-place on src) ----------------
__global__ void __launch_bounds__(128) add_ln_kernel(float* __restrict__ src, const float* __restrict__ res,
                                                     const float* __restrict__ g, const float* __restrict__ bta)
{
    int row = blockIdx.x;
    int tid = threadIdx.x;
    float x[3];
    float s = 0.f, sq = 0.f;
    #pragma unroll
    for (int i = 0; i < 3; i++) {
        int d = tid + i*128;
        float v = src[(size_t)row*DD + d] + res[(size_t)row*DD + d];
        x[i] = v; s += v; sq += v*v;
    }
    #pragma unroll
    for (int o = 16; o > 0; o >>= 1) {
        s  += __shfl_xor_sync(0xffffffffu, s,  o);
        sq += __shfl_xor_sync(0xffffffffu, sq, o);
    }
    __shared__ float ss[4], ssq[4];
    int w = tid >> 5;
    if ((tid & 31) == 0) { ss[w] = s; ssq[w] = sq; }
    __syncthreads();
    s  = ss[0]+ss[1]+ss[2]+ss[3];
    sq = ssq[0]+ssq[1]+ssq[2]+ssq[3];
    float mean = s * (1.f/384.f);
    float var  = sq * (1.f/384.f) - mean*mean;
    float rs = rsqrtf(var + 1e-5f);
    #pragma unroll
    for (int i = 0; i < 3; i++) {
        int d = tid + i*128;
        src[(size_t)row*DD + d] = (x[i]-mean)*rs*g[d] + bta[d];
    }
}

// ---------------- output slice ----------------
__global__ void copy_out_kernel(float* __restrict__ out)
{
    int idx = blockIdx.x*blockDim.x + threadIdx.x;
    if (idx >= BB*TT*DD) return;
    int d = idx % DD;
    int t = (idx/DD) % TT;
    int b = idx / (DD*TT);
    out[idx] = g_SRC[((size_t)(b*SS + (SS-TT) + t))*DD + d];
}

// ---------------- host launcher ----------------
extern "C" void kernel_launch(void* const* d_in, const int* in_sizes, int n_in,
                              void* d_out, int out_size)
{
    (void)in_sizes; (void)n_in; (void)out_size;
    const float* hand_t    = (const float*)d_in[0];
    const float* head_t    = (const float*)d_in[1];
    const float* hand_m1   = (const float*)d_in[2];
    const float* head_m1   = (const float*)d_in[3];
    const float* c_hand_t  = (const float*)d_in[4];
    const float* c_head_t  = (const float*)d_in[5];
    const float* c_hand_m1 = (const float*)d_in[6];
    const float* c_head_m1 = (const float*)d_in[7];
    const float* state_t   = (const float*)d_in[8];
    const float* state_m1  = (const float*)d_in[9];
    const float* tr_t      = (const float*)d_in[10];
    const float* tr_m1     = (const float*)d_in[11];
    const float* tok_m1    = (const float*)d_in[12];
    const float* tok_t     = (const float*)d_in[13];
    const float* Wq  = (const float*)d_in[14];
    const float* bq  = (const float*)d_in[15];
    const float* Wk  = (const float*)d_in[16];
    const float* bk  = (const float*)d_in[17];
    const float* Wv  = (const float*)d_in[18];
    const float* bv  = (const float*)d_in[19];
    const float* Wo  = (const float*)d_in[20];
    const float* bo  = (const float*)d_in[21];
    const float* W1  = (const float*)d_in[22];
    const float* b1  = (const float*)d_in[23];
    const float* W2  = (const float*)d_in[24];
    const float* b2  = (const float*)d_in[25];
    const float* g1  = (const float*)d_in[26];
    const float* be1 = (const float*)d_in[27];
    const float* g2  = (const float*)d_in[28];
    const float* be2 = (const float*)d_in[29];

    float *SRC, *Qp, *Kp, *Vp, *ATT, *PROJ, *FFB;
    cudaGetSymbolAddress((void**)&SRC,  g_SRC);
    cudaGetSymbolAddress((void**)&Qp,   g_Q);
    cudaGetSymbolAddress((void**)&Kp,   g_K);
    cudaGetSymbolAddress((void**)&Vp,   g_V);
    cudaGetSymbolAddress((void**)&ATT,  g_ATT);
    cudaGetSymbolAddress((void**)&PROJ, g_PROJ);
    cudaGetSymbolAddress((void**)&FFB,  g_FF);

    build_src_kernel<<<1024, 256>>>(hand_t, head_t, hand_m1, head_m1,
                                    state_t, state_m1, tok_m1, tok_t);
    build_coord_kernel<<<98, 256>>>(c_hand_t, c_head_t, c_hand_m1, c_head_m1, tr_t, tr_m1);

    dim3 gD(65, 3), gFF(65, 12);
    for (int l = 0; l < LL; l++) {
        size_t wsq = (size_t)l*DD*DD;
        sgemm_nt_kernel<false><<<gD, 256>>>(MM, DD, DD, SRC, Wq + wsq, bq + l*DD, Qp);
        sgemm_nt_kernel<false><<<gD, 256>>>(MM, DD, DD, SRC, Wk + wsq, bk + l*DD, Kp);
        sgemm_nt_kernel<false><<<gD, 256>>>(MM, DD, DD, SRC, Wv + wsq, bv + l*DD, Vp);
        rope_kernel<<<(BB*SS*HH + 255)/256, 256>>>();
        attn_kernel<<<dim3(17, 64), 256>>>(Qp, Kp, Vp, ATT);
        sgemm_nt_kernel<false><<<gD, 256>>>(MM, DD, DD, ATT, Wo + wsq, bo + l*DD, PROJ);
        add_ln_kernel<<<MM, 128>>>(SRC, PROJ, g1 + l*DD, be1 + l*DD);
        sgemm_nt_kernel<true ><<<gFF, 256>>>(MM, FFD, DD, SRC, W1 + (size_t)l*FFD*DD, b1 + l*FFD, FFB);
        sgemm_nt_kernel<false><<<gD, 256>>>(MM, DD, FFD, FFB, W2 + (size_t)l*DD*FFD, b2 + l*DD, PROJ);
        add_ln_kernel<<<MM, 128>>>(SRC, PROJ, g2 + l*DD, be2 + l*DD);
    }
    copy_out_kernel<<<48, 256>>>((float*)d_out);
}

// round 2
// speedup vs baseline: 1.4004x; 1.4004x over previous
#include <cuda_runtime.h>
#include <cuda_bf16.h>
#include <math.h>

// Problem constants
#define BB 8
#define NN 256
#define DD 384
#define LL 6
#define HH 8
#define FFD 1536
#define TT 4
#define DH 48
#define NM1 517
#define SS 1034
#define MM (BB*SS)   // 8272
#define QKVN 1152    // 3*DD

// ---------------- scratch (static device globals; no allocation) ----------------
__device__ float g_SRC [MM*DD];
__device__ float g_COORD[MM*3];
__device__ float g_QKV [MM*QKVN];
__device__ float g_ATT [MM*DD];
__device__ float g_PROJ[MM*DD];
__device__ float g_FF  [MM*FFD];

__device__ __nv_bfloat16 g_XH[MM*FFD];
__device__ __nv_bfloat16 g_XL[MM*FFD];

__device__ __nv_bfloat16 g_WqkvH[LL*QKVN*DD];
__device__ __nv_bfloat16 g_WqkvL[LL*QKVN*DD];
__device__ __nv_bfloat16 g_WoH[LL*DD*DD];
__device__ __nv_bfloat16 g_WoL[LL*DD*DD];
__device__ __nv_bfloat16 g_W1H[LL*FFD*DD];
__device__ __nv_bfloat16 g_W1L[LL*FFD*DD];
__device__ __nv_bfloat16 g_W2H[LL*DD*FFD];
__device__ __nv_bfloat16 g_W2L[LL*DD*FFD];
__device__ float g_bqkv[LL*QKVN];

// ---------------- input assembly ----------------
__global__ void build_src_kernel(const float* __restrict__ hand_t, const float* __restrict__ head_t,
                                 const float* __restrict__ hand_m1, const float* __restrict__ head_m1,
                                 const float* __restrict__ state_t, const float* __restrict__ state_m1,
                                 const float* __restrict__ tok_m1, const float* __restrict__ tok_t)
{
    for (int idx = blockIdx.x*blockDim.x + threadIdx.x; idx < BB*SS*DD; idx += gridDim.x*blockDim.x) {
        int d = idx % DD;
        int s = (idx / DD) % SS;
        int b = idx / (DD*SS);
        float v;
        if      (s == 0)    v = state_m1[b*DD + d];
        else if (s < 257)   v = hand_m1[((b*NN)+(s-1  ))*DD + d];
        else if (s < 513)   v = head_m1[((b*NN)+(s-257))*DD + d];
        else if (s < 517)   v = tok_m1[(s-513)*DD + d];
        else if (s == 517)  v = state_t[b*DD + d];
        else if (s < 774)   v = hand_t[((b*NN)+(s-518))*DD + d];
        else if (s < 1030)  v = head_t[((b*NN)+(s-774))*DD + d];
        else                v = tok_t[(s-1030)*DD + d];
        g_SRC[idx] = v;
    }
}

__global__ void build_coord_kernel(const float* __restrict__ c_hand_t, const float* __restrict__ c_head_t,
                                   const float* __restrict__ c_hand_m1, const float* __restrict__ c_head_m1,
                                   const float* __restrict__ tr_t, const float* __restrict__ tr_m1)
{
    for (int idx = blockIdx.x*blockDim.x + threadIdx.x; idx < BB*SS*3; idx += gridDim.x*blockDim.x) {
        int cdim = idx % 3;
        int s = (idx/3) % SS;
        int b = idx / (3*SS);
        float v;
        if      (s == 0)    v = tr_m1[b*3+cdim];
        else if (s < 257)   v = c_hand_m1[((b*NN)+(s-1  ))*3 + cdim];
        else if (s < 513)   v = c_head_m1[((b*NN)+(s-257))*3 + cdim];
        else if (s < 517)   v = tr_m1[b*3+cdim];
        else if (s == 517)  v = tr_t[b*3+cdim];
        else if (s < 774)   v = c_hand_t[((b*NN)+(s-518))*3 + cdim];
        else if (s < 1030)  v = c_head_t[((b*NN)+(s-774))*3 + cdim];
        else                v = tr_t[b*3+cdim];
        g_COORD[idx] = v;
    }
}

// ---------------- fp32 -> (bf16 hi, bf16 lo) split ----------------
__global__ void split_kernel(const float* __restrict__ x,
                             __nv_bfloat16* __restrict__ hi,
                             __nv_bfloat16* __restrict__ lo, int n)
{
    for (int i = blockIdx.x*blockDim.x + threadIdx.x; i < n; i += gridDim.x*blockDim.x) {
        float v = x[i];
        __nv_bfloat16 h = __float2bfloat16_rn(v);
        float r = v - __bfloat162float(h);
        hi[i] = h;
        lo[i] = __float2bfloat16_rn(r);
    }
}

// pack Wq/Wk/Wv into [L][1152][384] and split
__global__ void split_qkv_w_kernel(const float* __restrict__ Wq, const float* __restrict__ Wk,
                                   const float* __restrict__ Wv)
{
    const int total = LL*QKVN*DD;
    for (int idx = blockIdx.x*blockDim.x + threadIdx.x; idx < total; idx += gridDim.x*blockDim.x) {
        int k = idx % DD;
        int r = (idx / DD) % QKVN;
        int l = idx / (DD*QKVN);
        float v;
        if      (r < DD)    v = Wq[((size_t)l*DD + r      )*DD + k];
        else if (r < 2*DD)  v = Wk[((size_t)l*DD + r-DD   )*DD + k];
        else                v = Wv[((size_t)l*DD + r-2*DD )*DD + k];
        __nv_bfloat16 h = __float2bfloat16_rn(v);
        g_WqkvH[idx] = h;
        g_WqkvL[idx] = __float2bfloat16_rn(v - __bfloat162float(h));
    }
}

__global__ void pack_qkv_b_kernel(const float* __restrict__ bq, const float* __restrict__ bk,
                                  const float* __restrict__ bv)
{
    int idx = blockIdx.x*blockDim.x + threadIdx.x;
    if (idx >= LL*QKVN) return;
    int r = idx % QKVN;
    int l = idx / QKVN;
    float v;
    if      (r < DD)   v = bq[l*DD + r];
    else if (r < 2*DD) v = bk[l*DD + r-DD];
    else               v = bv[l*DD + r-2*DD];
    g_bqkv[idx] = v;
}

// ---------------- bf16x3 tensor-core GEMM ----------------
// C[m,n] = sum_k A[m,k]*W[n,k] + bias[n], A: M x K, W: N x K (both split into hi/lo bf16)
// tiles: BM=128, BN=128, BK=32; 256 threads = 8 warps (2 x 4), warp tile 64x32.
#define LDSMP 40   // padded smem row stride in bf16 elems (32 data + 8 pad)

__device__ __forceinline__ unsigned smem_addr(const void* p) {
    return (unsigned)__cvta_generic_to_shared(p);
}
__device__ __forceinline__ void ldsm_x4(unsigned r[4], unsigned addr) {
    asm volatile("ldmatrix.sync.aligned.m8n8.x4.shared.b16 {%0,%1,%2,%3}, [%4];"
                 : "=r"(r[0]), "=r"(r[1]), "=r"(r[2]), "=r"(r[3]) : "r"(addr));
}
__device__ __forceinline__ void mma_bf16(float c[4], const unsigned a[4], const unsigned b[2]) {
    asm volatile("mma.sync.aligned.m16n8k16.row.col.f32.bf16.bf16.f32 "
                 "{%0,%1,%2,%3}, {%4,%5,%6,%7}, {%8,%9}, {%0,%1,%2,%3};"
                 : "+f"(c[0]), "+f"(c[1]), "+f"(c[2]), "+f"(c[3])
                 : "r"(a[0]), "r"(a[1]), "r"(a[2]), "r"(a[3]), "r"(b[0]), "r"(b[1]));
}

template<bool DO_GELU>
__global__ void __launch_bounds__(256) gemm_kernel(int M, int N, int K,
    const __nv_bfloat16* __restrict__ Ah, const __nv_bfloat16* __restrict__ Al,
    const __nv_bfloat16* __restrict__ Wh, const __nv_bfloat16* __restrict__ Wl,
    const float* __restrict__ bias, float* __restrict__ C)
{
    __shared__ __nv_bfloat16 sAh[128*LDSMP], sAl[128*LDSMP];
    __shared__ __nv_bfloat16 sBh[128*LDSMP], sBl[128*LDSMP];

    const int tid  = threadIdx.x;
    const int lane = tid & 31;
    const int warp = tid >> 5;
    const int wm   = warp >> 2;          // 0..1
    const int wn   = warp & 3;           // 0..3
    const int m0   = blockIdx.x * 128;
    const int n0   = blockIdx.y * 128;

    float c[4][4][4];
    #pragma unroll
    for (int i = 0; i < 4; i++)
        #pragma unroll
        for (int j = 0; j < 4; j++)
            #pragma unroll
            for (int r = 0; r < 4; r++) c[i][j][r] = 0.f;

    // cooperative load indices: row = tid/4 (+64), colChunk = (tid%4)*8
    const int lr = tid >> 2;
    const int lc = (tid & 3) * 8;

    // ldmatrix lane geometry
    const int aRow    = wm*64 + (lane & 7) + ((lane >> 3) & 1) * 8;   // + mt*16
    const int aColSel = (lane >> 4) * 8;                              // + kk*16
    const int bRow    = wn*32 + (lane & 7) + ((lane >> 4) & 1) * 8;   // + np*16
    const int bColSel = ((lane >> 3) & 1) * 8;                        // + kk*16

    const unsigned sAh_b = smem_addr(sAh), sAl_b = smem_addr(sAl);
    const unsigned sBh_b = smem_addr(sBh), sBl_b = smem_addr(sBl);

    for (int kt = 0; kt < K; kt += 32) {
        __syncthreads();
        #pragma unroll
        for (int half = 0; half < 2; half++) {
            int r = lr + half*64;
            int gm = m0 + r;
            uint4 vh = make_uint4(0,0,0,0), vl = vh;
            if (gm < M) {
                vh = *(const uint4*)(Ah + (size_t)gm*K + kt + lc);
                vl = *(const uint4*)(Al + (size_t)gm*K + kt + lc);
            }
            *(uint4*)&sAh[r*LDSMP + lc] = vh;
            *(uint4*)&sAl[r*LDSMP + lc] = vl;
            *(uint4*)&sBh[r*LDSMP + lc] = *(const uint4*)(Wh + (size_t)(n0 + r)*K + kt + lc);
            *(uint4*)&sBl[r*LDSMP + lc] = *(const uint4*)(Wl + (size_t)(n0 + r)*K + kt + lc);
        }
        __syncthreads();

        #pragma unroll
        for (int kk = 0; kk < 2; kk++) {
            unsigned ah[4][4], al[4][4], bh[4][2], bl[4][2];
            #pragma unroll
            for (int mt = 0; mt < 4; mt++) {
                unsigned off = (unsigned)(((aRow + mt*16)*LDSMP + kk*16 + aColSel) * 2);
                ldsm_x4(ah[mt], sAh_b + off);
                ldsm_x4(al[mt], sAl_b + off);
            }
            #pragma unroll
            for (int np = 0; np < 2; np++) {
                unsigned off = (unsigned)(((bRow + np*16)*LDSMP + kk*16 + bColSel) * 2);
                unsigned t[4];
                ldsm_x4(t, sBh_b + off);
                bh[2*np][0]=t[0]; bh[2*np][1]=t[1]; bh[2*np+1][0]=t[2]; bh[2*np+1][1]=t[3];
                ldsm_x4(t, sBl_b + off);
                bl[2*np][0]=t[0]; bl[2*np][1]=t[1]; bl[2*np+1][0]=t[2]; bl[2*np+1][1]=t[3];
            }
            #pragma unroll
            for (int mt = 0; mt < 4; mt++)
                #pragma unroll
                for (int nt = 0; nt < 4; nt++) {
                    mma_bf16(c[mt][nt], ah[mt], bh[nt]);
                    mma_bf16(c[mt][nt], al[mt], bh[nt]);
                    mma_bf16(c[mt][nt], ah[mt], bl[nt]);
                }
        }
    }

    // epilogue
    #pragma unroll
    for (int mt = 0; mt < 4; mt++) {
        #pragma unroll
        for (int nt = 0; nt < 4; nt++) {
            int col  = n0 + wn*32 + nt*8 + (lane & 3)*2;
            float b0 = bias[col], b1 = bias[col+1];
            int row0 = m0 + wm*64 + mt*16 + (lane >> 2);
            int row1 = row0 + 8;
            float v0 = c[mt][nt][0] + b0, v1 = c[mt][nt][1] + b1;
            float v2 = c[mt][nt][2] + b0, v3 = c[mt][nt][3] + b1;
            if (DO_GELU) {
                v0 = 0.5f*v0*(1.0f+erff(v0*0.7071067811865475f));
                v1 = 0.5f*v1*(1.0f+erff(v1*0.7071067811865475f));
                v2 = 0.5f*v2*(1.0f+erff(v2*0.7071067811865475f));
                v3 = 0.5f*v3*(1.0f+erff(v3*0.7071067811865475f));
            }
            if (row0 < M) *(float2*)&C[(size_t)row0*N + col] = make_float2(v0, v1);
            if (row1 < M) *(float2*)&C[(size_t)row1*N + col] = make_float2(v2, v3);
        }
    }
}

// ---------------- rotary PE (in-place on packed QKV: Q at col 0, K at col 384) ----------------
__global__ void rope_kernel()
{
    int idx = blockIdx.x*blockDim.x + threadIdx.x;
    if (idx >= BB*SS*HH) return;
    int h = idx % HH;
    int s = (idx/HH) % SS;
    int b = idx / (HH*SS);
    size_t base = ((size_t)(b*SS + s))*QKVN + h*DH;

    float invf[8];
    #pragma unroll
    for (int j = 0; j < 8; j++)
        invf[j] = exp2f(-1.6609640474436813f * (float)j);  // 10000^(-j/8)

    #pragma unroll
    for (int a = 0; a < 3; a++) {
        float co = g_COORD[(b*SS+s)*3 + a];
        #pragma unroll
        for (int j = 0; j < 8; j++) {
            float ang = co * invf[j];
            float cs = cosf(ang), sn = sinf(ang);
            size_t i1 = base + a*16 + j, i2 = i1 + 8;
            float q1 = g_QKV[i1], q2 = g_QKV[i2];
            g_QKV[i1] = q1*cs - q2*sn;  g_QKV[i2] = q1*sn + q2*cs;
            size_t k1i = i1 + DD, k2i = i2 + DD;
            float k1 = g_QKV[k1i], k2 = g_QKV[k2i];
            g_QKV[k1i] = k1*cs - k2*sn;  g_QKV[k2i] = k1*sn + k2*cs;
        }
    }
}

// ---------------- flash attention (reads packed QKV, writes ATT [M x D]) ----------------
__global__ void __launch_bounds__(256) attn_kernel(const float* __restrict__ QKV,
                                                   float* __restrict__ O)
{
    const int bh = blockIdx.y;
    const int b = bh >> 3, h = bh & 7;
    const int q0 = blockIdx.x * 64;
    const int tid = threadIdx.x;
    const int r = tid >> 2, c = tid & 3;
    const int qrow = q0 + r;

    __shared__ float Ks[64*52];
    __shared__ float Vs[64*52];

    const float scale = 0.14433756729740643f; // 1/sqrt(48)
    float qreg[48];
    {
        int qr = qrow < SS ? qrow : SS-1;
        const float* qp = QKV + ((size_t)(b*SS + qr))*QKVN + h*DH;
        #pragma unroll
        for (int i = 0; i < 12; i++) {
            float4 t = *(const float4*)(qp + i*4);
            qreg[i*4+0]=t.x*scale; qreg[i*4+1]=t.y*scale; qreg[i*4+2]=t.z*scale; qreg[i*4+3]=t.w*scale;
        }
    }

    float m_i = -INFINITY, l_i = 0.f;
    float acc[48];
    #pragma unroll
    for (int i = 0; i < 48; i++) acc[i] = 0.f;

    const size_t baseK = (size_t)b*SS*QKVN + DD   + h*DH;
    const size_t baseV = (size_t)b*SS*QKVN + 2*DD + h*DH;

    for (int kt = 0; kt < 17; kt++) {
        int k0 = kt * 64;
        if ((q0 + 63 < NM1) && (k0 >= NM1)) continue;

        __syncthreads();
        #pragma unroll
        for (int it = 0; it < 3; it++) {
            int idx = tid + it*256;
            int row = idx / 12, f4 = (idx % 12)*4;
            int kg = k0 + row;
            float4 kv, vv;
            if (kg < SS) {
                kv = *(const float4*)(QKV + baseK + (size_t)kg*QKVN + f4);
                vv = *(const float4*)(QKV + baseV + (size_t)kg*QKVN + f4);
            } else {
                kv = make_float4(0.f,0.f,0.f,0.f); vv = kv;
            }
            *(float4*)&Ks[row*52 + f4] = kv;
            *(float4*)&Vs[row*52 + f4] = vv;
        }
        __syncthreads();

        float p[16];
        float tmax = -INFINITY;
        #pragma unroll
        for (int kk = 0; kk < 16; kk++) {
            int kl = c + 4*kk;
            int kg = k0 + kl;
            const float* kp = &Ks[kl*52];
            float dot = 0.f;
            #pragma unroll
            for (int i = 0; i < 48; i++) dot += qreg[i]*kp[i];
            bool masked = (kg >= SS) || (qrow < NM1 && kg >= NM1);
            p[kk] = masked ? -INFINITY : dot;
            tmax = fmaxf(tmax, p[kk]);
        }
        tmax = fmaxf(tmax, __shfl_xor_sync(0xffffffffu, tmax, 1));
        tmax = fmaxf(tmax, __shfl_xor_sync(0xffffffffu, tmax, 2));
        float newm = fmaxf(m_i, tmax);
        float factor = __expf(m_i - newm);
        m_i = newm;

        float psum = 0.f;
        #pragma unroll
        for (int kk = 0; kk < 16; kk++) { p[kk] = __expf(p[kk] - m_i); psum += p[kk]; }
        psum += __shfl_xor_sync(0xffffffffu, psum, 1);
        psum += __shfl_xor_sync(0xffffffffu, psum, 2);
        l_i = l_i * factor + psum;

        #pragma unroll
        for (int i = 0; i < 48; i++) acc[i] *= factor;

        #pragma unroll
        for (int kk = 0; kk < 16; kk++) {
            float pv = p[kk];
            if (pv > 0.f) {
                const float* vp = &Vs[(c + 4*kk)*52];
                #pragma unroll
                for (int i = 0; i < 48; i++) acc[i] += pv*vp[i];
            }
        }
    }

    #pragma unroll
    for (int i = 0; i < 48; i++) {
        float v = acc[i];
        v += __shfl_xor_sync(0xffffffffu, v, 1);
        v += __shfl_xor_sync(0xffffffffu, v, 2);
        acc[i] = v;
    }
    if (c == 0 && qrow < SS) {
        float inv_l = 1.f / l_i;
        float* op = O + ((size_t)(b*SS + qrow))*DD + h*DH;
        #pragma unroll
        for (int i = 0; i < 12; i++) {
            float4 o;
            o.x = acc[i*4+0]*inv_l; o.y = acc[i*4+1]*inv_l;
            o.z = acc[i*4+2]*inv_l; o.w = acc[i*4+3]*inv_l;
            *(float4*)(op + i*4) = o;
        }
    }
}

// ---------------- residual add + layernorm (in-place on src) ----------------
__global__ void __launch_bounds__(128) add_ln_kernel(float* __restrict__ src, const float* __restrict__ res,
                                                     const float* __restrict__ g, const float* __restrict__ bta)
{
    int row = blockIdx.x;
    int tid = threadIdx.x;
    float x[3];
    float s = 0.f, sq = 0.f;
    #pragma unroll
    for (int i = 0; i < 3; i++) {
        int d = tid + i*128;
        float v = src[(size_t)row*DD + d] + res[(size_t)row*DD + d];
        x[i] = v; s += v; sq += v*v;
    }
    #pragma unroll
    for (int o = 16; o > 0; o >>= 1) {
        s  += __shfl_xor_sync(0xffffffffu, s,  o);
        sq += __shfl_xor_sync(0xffffffffu, sq, o);
    }
    __shared__ float ss[4], ssq[4];
    int w = tid >> 5;
    if ((tid & 31) == 0) { ss[w] = s; ssq[w] = sq; }
    __syncthreads();
    s  = ss[0]+ss[1]+ss[2]+ss[3];
    sq = ssq[0]+ssq[1]+ssq[2]+ssq[3];
    float mean = s * (1.f/384.f);
    float var  = sq * (1.f/384.f) - mean*mean;
    float rs = rsqrtf(var + 1e-5f);
    #pragma unroll
    for (int i = 0; i < 3; i++) {
        int d = tid + i*128;
        src[(size_t)row*DD + d] = (x[i]-mean)*rs*g[d] + bta[d];
    }
}

// ---------------- output slice ----------------
__global__ void copy_out_kernel(float* __restrict__ out)
{
    int idx = blockIdx.x*blockDim.x + threadIdx.x;
    if (idx >= BB*TT*DD) return;
    int d = idx % DD;
    int t = (idx/DD) % TT;
    int b = idx / (DD*TT);
    out[idx] = g_SRC[((size_t)(b*SS + (SS-TT) + t))*DD + d];
}

// ---------------- host launcher ----------------
extern "C" void kernel_launch(void* const* d_in, const int* in_sizes, int n_in,
                              void* d_out, int out_size)
{
    (void)in_sizes; (void)n_in; (void)out_size;
    const float* hand_t    = (const float*)d_in[0];
    const float* head_t    = (const float*)d_in[1];
    const float* hand_m1   = (const float*)d_in[2];
    const float* head_m1   = (const float*)d_in[3];
    const float* c_hand_t  = (const float*)d_in[4];
    const float* c_head_t  = (const float*)d_in[5];
    const float* c_hand_m1 = (const float*)d_in[6];
    const float* c_head_m1 = (const float*)d_in[7];
    const float* state_t   = (const float*)d_in[8];
    const float* state_m1  = (const float*)d_in[9];
    const float* tr_t      = (const float*)d_in[10];
    const float* tr_m1     = (const float*)d_in[11];
    const float* tok_m1    = (const float*)d_in[12];
    const float* tok_t     = (const float*)d_in[13];
    const float* Wq  = (const float*)d_in[14];
    const float* bq  = (const float*)d_in[15];
    const float* Wk  = (const float*)d_in[16];
    const float* bk  = (const float*)d_in[17];
    const float* Wv  = (const float*)d_in[18];
    const float* bv  = (const float*)d_in[19];
    const float* Wo  = (const float*)d_in[20];
    const float* bo  = (const float*)d_in[21];
    const float* W1  = (const float*)d_in[22];
    const float* b1  = (const float*)d_in[23];
    const float* W2  = (const float*)d_in[24];
    const float* b2  = (const float*)d_in[25];
    const float* g1  = (const float*)d_in[26];
    const float* be1 = (const float*)d_in[27];
    const float* g2  = (const float*)d_in[28];
    const float* be2 = (const float*)d_in[29];

    float *SRC, *QKVp, *ATT, *PROJ, *FFB, *BQKV;
    __nv_bfloat16 *XH, *XL, *WqkvH, *WqkvL, *WoH, *WoL, *W1H, *W1L, *W2H, *W2L;
    cudaGetSymbolAddress((void**)&SRC,   g_SRC);
    cudaGetSymbolAddress((void**)&QKVp,  g_QKV);
    cudaGetSymbolAddress((void**)&ATT,   g_ATT);
    cudaGetSymbolAddress((void**)&PROJ,  g_PROJ);
    cudaGetSymbolAddress((void**)&FFB,   g_FF);
    cudaGetSymbolAddress((void**)&XH,    g_XH);
    cudaGetSymbolAddress((void**)&XL,    g_XL);
    cudaGetSymbolAddress((void**)&WqkvH, g_WqkvH);
    cudaGetSymbolAddress((void**)&WqkvL, g_WqkvL);
    cudaGetSymbolAddress((void**)&WoH,   g_WoH);
    cudaGetSymbolAddress((void**)&WoL,   g_WoL);
    cudaGetSymbolAddress((void**)&W1H,   g_W1H);
    cudaGetSymbolAddress((void**)&W1L,   g_W1L);
    cudaGetSymbolAddress((void**)&W2H,   g_W2H);
    cudaGetSymbolAddress((void**)&W2L,   g_W2L);
    cudaGetSymbolAddress((void**)&BQKV,  g_bqkv);

    // assemble inputs
    build_src_kernel<<<1024, 256>>>(hand_t, head_t, hand_m1, head_m1,
                                    state_t, state_m1, tok_m1, tok_t);
    build_coord_kernel<<<98, 256>>>(c_hand_t, c_head_t, c_hand_m1, c_head_m1, tr_t, tr_m1);

    // split / pack all weights once
    split_qkv_w_kernel<<<2048, 256>>>(Wq, Wk, Wv);
    pack_qkv_b_kernel<<<(LL*QKVN + 255)/256, 256>>>(bq, bk, bv);
    split_kernel<<<2048, 256>>>(Wo, WoH, WoL, LL*DD*DD);
    split_kernel<<<2048, 256>>>(W1, W1H, W1L, LL*FFD*DD);
    split_kernel<<<2048, 256>>>(W2, W2H, W2L, LL*DD*FFD);

    const int MB = (MM + 127)/128;   // 65
    for (int l = 0; l < LL; l++) {
        // QKV
        split_kernel<<<2048, 256>>>(SRC, XH, XL, MM*DD);
        gemm_kernel<false><<<dim3(MB, QKVN/128), 256>>>(MM, QKVN, DD, XH, XL,
            WqkvH + (size_t)l*QKVN*DD, WqkvL + (size_t)l*QKVN*DD, BQKV + l*QKVN, QKVp);
        rope_kernel<<<(BB*SS*HH + 255)/256, 256>>>();
        attn_kernel<<<dim3(17, 64), 256>>>(QKVp, ATT);
        // Wo
        split_kernel<<<2048, 256>>>(ATT, XH, XL, MM*DD);
        gemm_kernel<false><<<dim3(MB, DD/128), 256>>>(MM, DD, DD, XH, XL,
            WoH + (size_t)l*DD*DD, WoL + (size_t)l*DD*DD, bo + l*DD, PROJ);
        add_ln_kernel<<<MM, 128>>>(SRC, PROJ, g1 + l*DD, be1 + l*DD);
        // FF
        split_kernel<<<2048, 256>>>(SRC, XH, XL, MM*DD);
        gemm_kernel<true><<<dim3(MB, FFD/128), 256>>>(MM, FFD, DD, XH, XL,
            W1H + (size_t)l*FFD*DD, W1L + (size_t)l*FFD*DD, b1 + l*FFD, FFB);
        split_kernel<<<2048, 256>>>(FFB, XH, XL, MM*FFD);
        gemm_kernel<false><<<dim3(MB, DD/128), 256>>>(MM, DD, FFD, XH, XL,
            W2H + (size_t)l*DD*FFD, W2L + (size_t)l*DD*FFD, b2 + l*DD, PROJ);
        add_ln_kernel<<<MM, 128>>>(SRC, PROJ, g2 + l*DD, be2 + l*DD);
    }
    copy_out_kernel<<<48, 256>>>((float*)d_out);
}

// round 3
// speedup vs baseline: 2.4438x; 1.7451x over previous
#include <cuda_runtime.h>
#include <cuda_bf16.h>
#include <math.h>

// Problem constants
#define BB 8
#define NN 256
#define DD 384
#define LL 6
#define HH 8
#define FFD 1536
#define TT 4
#define DH 48
#define NM1 517
#define SS 1034
#define MM (BB*SS)   // 8272
#define QKVN 1152    // 3*DD

// ---------------- scratch (static device globals; no allocation) ----------------
__device__ float g_SRC [MM*DD];
__device__ float g_COORD[MM*3];
__device__ float g_QKV [MM*QKVN];
__device__ float g_PROJ[MM*DD];

__device__ __nv_bfloat16 g_XH[MM*DD];
__device__ __nv_bfloat16 g_XL[MM*DD];
__device__ __nv_bfloat16 g_FFH[MM*FFD];
__device__ __nv_bfloat16 g_FFL[MM*FFD];

__device__ __nv_bfloat16 g_WqkvH[LL*QKVN*DD];
__device__ __nv_bfloat16 g_WqkvL[LL*QKVN*DD];
__device__ __nv_bfloat16 g_WoH[LL*DD*DD];
__device__ __nv_bfloat16 g_WoL[LL*DD*DD];
__device__ __nv_bfloat16 g_W1H[LL*FFD*DD];
__device__ __nv_bfloat16 g_W1L[LL*FFD*DD];
__device__ __nv_bfloat16 g_W2H[LL*DD*FFD];
__device__ __nv_bfloat16 g_W2L[LL*DD*FFD];
__device__ float g_bqkv[LL*QKVN];

// ---------------- input assembly ----------------
__global__ void build_src_kernel(const float* __restrict__ hand_t, const float* __restrict__ head_t,
                                 const float* __restrict__ hand_m1, const float* __restrict__ head_m1,
                                 const float* __restrict__ state_t, const float* __restrict__ state_m1,
                                 const float* __restrict__ tok_m1, const float* __restrict__ tok_t)
{
    for (int idx = blockIdx.x*blockDim.x + threadIdx.x; idx < BB*SS*DD; idx += gridDim.x*blockDim.x) {
        int d = idx % DD;
        int s = (idx / DD) % SS;
        int b = idx / (DD*SS);
        float v;
        if      (s == 0)    v = state_m1[b*DD + d];
        else if (s < 257)   v = hand_m1[((b*NN)+(s-1  ))*DD + d];
        else if (s < 513)   v = head_m1[((b*NN)+(s-257))*DD + d];
        else if (s < 517)   v = tok_m1[(s-513)*DD + d];
        else if (s == 517)  v = state_t[b*DD + d];
        else if (s < 774)   v = hand_t[((b*NN)+(s-518))*DD + d];
        else if (s < 1030)  v = head_t[((b*NN)+(s-774))*DD + d];
        else                v = tok_t[(s-1030)*DD + d];
        g_SRC[idx] = v;
    }
}

__global__ void build_coord_kernel(const float* __restrict__ c_hand_t, const float* __restrict__ c_head_t,
                                   const float* __restrict__ c_hand_m1, const float* __restrict__ c_head_m1,
                                   const float* __restrict__ tr_t, const float* __restrict__ tr_m1)
{
    for (int idx = blockIdx.x*blockDim.x + threadIdx.x; idx < BB*SS*3; idx += gridDim.x*blockDim.x) {
        int cdim = idx % 3;
        int s = (idx/3) % SS;
        int b = idx / (3*SS);
        float v;
        if      (s == 0)    v = tr_m1[b*3+cdim];
        else if (s < 257)   v = c_hand_m1[((b*NN)+(s-1  ))*3 + cdim];
        else if (s < 513)   v = c_head_m1[((b*NN)+(s-257))*3 + cdim];
        else if (s < 517)   v = tr_m1[b*3+cdim];
        else if (s == 517)  v = tr_t[b*3+cdim];
        else if (s < 774)   v = c_hand_t[((b*NN)+(s-518))*3 + cdim];
        else if (s < 1030)  v = c_head_t[((b*NN)+(s-774))*3 + cdim];
        else                v = tr_t[b*3+cdim];
        g_COORD[idx] = v;
    }
}

// ---------------- fp32 -> (bf16 hi, bf16 lo) split ----------------
__global__ void split_kernel(const float* __restrict__ x,
                             __nv_bfloat16* __restrict__ hi,
                             __nv_bfloat16* __restrict__ lo, int n)
{
    for (int i = blockIdx.x*blockDim.x + threadIdx.x; i < n; i += gridDim.x*blockDim.x) {
        float v = x[i];
        __nv_bfloat16 h = __float2bfloat16_rn(v);
        float r = v - __bfloat162float(h);
        hi[i] = h;
        lo[i] = __float2bfloat16_rn(r);
    }
}

// pack Wq/Wk/Wv into [L][1152][384] and split
__global__ void split_qkv_w_kernel(const float* __restrict__ Wq, const float* __restrict__ Wk,
                                   const float* __restrict__ Wv)
{
    const int total = LL*QKVN*DD;
    for (int idx = blockIdx.x*blockDim.x + threadIdx.x; idx < total; idx += gridDim.x*blockDim.x) {
        int k = idx % DD;
        int r = (idx / DD) % QKVN;
        int l = idx / (DD*QKVN);
        float v;
        if      (r < DD)    v = Wq[((size_t)l*DD + r      )*DD + k];
        else if (r < 2*DD)  v = Wk[((size_t)l*DD + r-DD   )*DD + k];
        else                v = Wv[((size_t)l*DD + r-2*DD )*DD + k];
        __nv_bfloat16 h = __float2bfloat16_rn(v);
        g_WqkvH[idx] = h;
        g_WqkvL[idx] = __float2bfloat16_rn(v - __bfloat162float(h));
    }
}

__global__ void pack_qkv_b_kernel(const float* __restrict__ bq, const float* __restrict__ bk,
                                  const float* __restrict__ bv)
{
    int idx = blockIdx.x*blockDim.x + threadIdx.x;
    if (idx >= LL*QKVN) return;
    int r = idx % QKVN;
    int l = idx / QKVN;
    float v;
    if      (r < DD)   v = bq[l*DD + r];
    else if (r < 2*DD) v = bk[l*DD + r-DD];
    else               v = bv[l*DD + r-2*DD];
    g_bqkv[idx] = v;
}

// ---------------- mma helpers ----------------
__device__ __forceinline__ unsigned smem_addr(const void* p) {
    return (unsigned)__cvta_generic_to_shared(p);
}
__device__ __forceinline__ void ldsm_x4(unsigned r[4], unsigned addr) {
    asm volatile("ldmatrix.sync.aligned.m8n8.x4.shared.b16 {%0,%1,%2,%3}, [%4];"
                 : "=r"(r[0]), "=r"(r[1]), "=r"(r[2]), "=r"(r[3]) : "r"(addr));
}
__device__ __forceinline__ void mma_bf16(float c[4], const unsigned a[4], const unsigned b[2]) {
    asm volatile("mma.sync.aligned.m16n8k16.row.col.f32.bf16.bf16.f32 "
                 "{%0,%1,%2,%3}, {%4,%5,%6,%7}, {%8,%9}, {%0,%1,%2,%3};"
                 : "+f"(c[0]), "+f"(c[1]), "+f"(c[2]), "+f"(c[3])
                 : "r"(a[0]), "r"(a[1]), "r"(a[2]), "r"(a[3]), "r"(b[0]), "r"(b[1]));
}
// pack two fp32 into bf16x2 hi + residual bf16x2 lo
__device__ __forceinline__ void split2(float a, float b, unsigned &h, unsigned &l) {
    __nv_bfloat162 hh = __floats2bfloat162_rn(a, b);
    h = *(unsigned*)&hh;
    float ra = a - __bfloat162float(hh.x);
    float rb = b - __bfloat162float(hh.y);
    __nv_bfloat162 ll = __floats2bfloat162_rn(ra, rb);
    l = *(unsigned*)&ll;
}

// ---------------- bf16x3 tensor-core GEMM ----------------
// C[m,n] = sum_k A[m,k]*W[n,k] + bias[n]
#define LDSMP 40   // padded smem row stride in bf16 elems

template<bool DO_GELU, bool SPLIT_OUT>
__global__ void __launch_bounds__(256) gemm_kernel(int M, int N, int K,
    const __nv_bfloat16* __restrict__ Ah, const __nv_bfloat16* __restrict__ Al,
    const __nv_bfloat16* __restrict__ Wh, const __nv_bfloat16* __restrict__ Wl,
    const float* __restrict__ bias, float* __restrict__ C,
    __nv_bfloat16* __restrict__ Ch, __nv_bfloat16* __restrict__ Cl)
{
    __shared__ __nv_bfloat16 sAh[128*LDSMP], sAl[128*LDSMP];
    __shared__ __nv_bfloat16 sBh[128*LDSMP], sBl[128*LDSMP];

    const int tid  = threadIdx.x;
    const int lane = tid & 31;
    const int warp = tid >> 5;
    const int wm   = warp >> 2;          // 0..1
    const int wn   = warp & 3;           // 0..3
    const int m0   = blockIdx.x * 128;
    const int n0   = blockIdx.y * 128;

    float c[4][4][4];
    #pragma unroll
    for (int i = 0; i < 4; i++)
        #pragma unroll
        for (int j = 0; j < 4; j++)
            #pragma unroll
            for (int r = 0; r < 4; r++) c[i][j][r] = 0.f;

    const int lr = tid >> 2;
    const int lc = (tid & 3) * 8;

    const int aRow    = wm*64 + (lane & 7) + ((lane >> 3) & 1) * 8;
    const int aColSel = (lane >> 4) * 8;
    const int bRow    = wn*32 + (lane & 7) + ((lane >> 4) & 1) * 8;
    const int bColSel = ((lane >> 3) & 1) * 8;

    const unsigned sAh_b = smem_addr(sAh), sAl_b = smem_addr(sAl);
    const unsigned sBh_b = smem_addr(sBh), sBl_b = smem_addr(sBl);

    for (int kt = 0; kt < K; kt += 32) {
        __syncthreads();
        #pragma unroll
        for (int half = 0; half < 2; half++) {
            int r = lr + half*64;
            int gm = m0 + r;
            uint4 vh = make_uint4(0,0,0,0), vl = vh;
            if (gm < M) {
                vh = *(const uint4*)(Ah + (size_t)gm*K + kt + lc);
                vl = *(const uint4*)(Al + (size_t)gm*K + kt + lc);
            }
            *(uint4*)&sAh[r*LDSMP + lc] = vh;
            *(uint4*)&sAl[r*LDSMP + lc] = vl;
            *(uint4*)&sBh[r*LDSMP + lc] = *(const uint4*)(Wh + (size_t)(n0 + r)*K + kt + lc);
            *(uint4*)&sBl[r*LDSMP + lc] = *(const uint4*)(Wl + (size_t)(n0 + r)*K + kt + lc);
        }
        __syncthreads();

        #pragma unroll
        for (int kk = 0; kk < 2; kk++) {
            unsigned ah[4][4], al[4][4], bh[4][2], bl[4][2];
            #pragma unroll
            for (int mt = 0; mt < 4; mt++) {
                unsigned off = (unsigned)(((aRow + mt*16)*LDSMP + kk*16 + aColSel) * 2);
                ldsm_x4(ah[mt], sAh_b + off);
                ldsm_x4(al[mt], sAl_b + off);
            }
            #pragma unroll
            for (int np = 0; np < 2; np++) {
                unsigned off = (unsigned)(((bRow + np*16)*LDSMP + kk*16 + bColSel) * 2);
                unsigned t[4];
                ldsm_x4(t, sBh_b + off);
                bh[2*np][0]=t[0]; bh[2*np][1]=t[1]; bh[2*np+1][0]=t[2]; bh[2*np+1][1]=t[3];
                ldsm_x4(t, sBl_b + off);
                bl[2*np][0]=t[0]; bl[2*np][1]=t[1]; bl[2*np+1][0]=t[2]; bl[2*np+1][1]=t[3];
            }
            #pragma unroll
            for (int mt = 0; mt < 4; mt++)
                #pragma unroll
                for (int nt = 0; nt < 4; nt++) {
                    mma_bf16(c[mt][nt], ah[mt], bh[nt]);
                    mma_bf16(c[mt][nt], al[mt], bh[nt]);
                    mma_bf16(c[mt][nt], ah[mt], bl[nt]);
                }
        }
    }

    #pragma unroll
    for (int mt = 0; mt < 4; mt++) {
        #pragma unroll
        for (int nt = 0; nt < 4; nt++) {
            int col  = n0 + wn*32 + nt*8 + (lane & 3)*2;
            float b0 = bias[col], b1 = bias[col+1];
            int row0 = m0 + wm*64 + mt*16 + (lane >> 2);
            int row1 = row0 + 8;
            float v0 = c[mt][nt][0] + b0, v1 = c[mt][nt][1] + b1;
            float v2 = c[mt][nt][2] + b0, v3 = c[mt][nt][3] + b1;
            if (DO_GELU) {
                v0 = 0.5f*v0*(1.0f+erff(v0*0.7071067811865475f));
                v1 = 0.5f*v1*(1.0f+erff(v1*0.7071067811865475f));
                v2 = 0.5f*v2*(1.0f+erff(v2*0.7071067811865475f));
                v3 = 0.5f*v3*(1.0f+erff(v3*0.7071067811865475f));
            }
            if (SPLIT_OUT) {
                unsigned h01, l01, h23, l23;
                split2(v0, v1, h01, l01);
                split2(v2, v3, h23, l23);
                if (row0 < M) { *(unsigned*)&Ch[(size_t)row0*N + col] = h01;
                                *(unsigned*)&Cl[(size_t)row0*N + col] = l01; }
                if (row1 < M) { *(unsigned*)&Ch[(size_t)row1*N + col] = h23;
                                *(unsigned*)&Cl[(size_t)row1*N + col] = l23; }
            } else {
                if (row0 < M) *(float2*)&C[(size_t)row0*N + col] = make_float2(v0, v1);
                if (row1 < M) *(float2*)&C[(size_t)row1*N + col] = make_float2(v2, v3);
            }
        }
    }
}

// ---------------- rotary PE (in-place on packed QKV) ----------------
__global__ void rope_kernel()
{
    int idx = blockIdx.x*blockDim.x + threadIdx.x;
    if (idx >= BB*SS*HH) return;
    int h = idx % HH;
    int s = (idx/HH) % SS;
    int b = idx / (HH*SS);
    size_t base = ((size_t)(b*SS + s))*QKVN + h*DH;

    float invf[8];
    #pragma unroll
    for (int j = 0; j < 8; j++)
        invf[j] = exp2f(-1.6609640474436813f * (float)j);

    #pragma unroll
    for (int a = 0; a < 3; a++) {
        float co = g_COORD[(b*SS+s)*3 + a];
        #pragma unroll
        for (int j = 0; j < 8; j++) {
            float ang = co * invf[j];
            float cs = cosf(ang), sn = sinf(ang);
            size_t i1 = base + a*16 + j, i2 = i1 + 8;
            float q1 = g_QKV[i1], q2 = g_QKV[i2];
            g_QKV[i1] = q1*cs - q2*sn;  g_QKV[i2] = q1*sn + q2*cs;
            size_t k1i = i1 + DD, k2i = i2 + DD;
            float k1 = g_QKV[k1i], k2 = g_QKV[k2i];
            g_QKV[k1i] = k1*cs - k2*sn;  g_QKV[k2i] = k1*sn + k2*cs;
        }
    }
}

// ---------------- tensor-core flash attention ----------------
// grid (17 q-tiles, B*H), 128 threads = 4 warps. Each warp: 16 q-rows.
// Q,K: bf16 hi/lo split; Q*K^T 3-term; softmax fp32; P*V 3-term (P split, V split).
// Output written directly as bf16 hi/lo (input for Wo gemm).
#define QKP 56  // Q/K smem row stride (bf16)
#define VTP 72  // Vt smem row stride (bf16)

__global__ void __launch_bounds__(128) attn_mma_kernel(const float* __restrict__ QKV,
                                                       __nv_bfloat16* __restrict__ AH,
                                                       __nv_bfloat16* __restrict__ AL)
{
    const int bh = blockIdx.y;
    const int b = bh >> 3, h = bh & 7;
    const int q0 = blockIdx.x * 64;
    const int tid = threadIdx.x;
    const int lane = tid & 31;
    const int warp = tid >> 5;

    __shared__ __nv_bfloat16 sQh[64*QKP], sQl[64*QKP];
    __shared__ __nv_bfloat16 sKh[64*QKP], sKl[64*QKP];
    __shared__ __nv_bfloat16 sVh[48*VTP], sVl[48*VTP];

    const float scale = 0.14433756729740643f; // 1/sqrt(48)
    const size_t baseQ = (size_t)b*SS*QKVN + h*DH;
    const size_t baseK = baseQ + DD;
    const size_t baseV = baseQ + 2*DD;

    // stage Q (scaled + split)
    #pragma unroll
    for (int i = 0; i < 6; i++) {
        int idx = tid + i*128;
        int row = idx / 12, c4 = (idx % 12) * 4;
        int qg = q0 + row;
        float4 v = make_float4(0.f,0.f,0.f,0.f);
        if (qg < SS) v = *(const float4*)(QKV + baseQ + (size_t)qg*QKVN + c4);
        float vv[4] = {v.x*scale, v.y*scale, v.z*scale, v.w*scale};
        #pragma unroll
        for (int j = 0; j < 4; j++) {
            __nv_bfloat16 hh = __float2bfloat16_rn(vv[j]);
            sQh[row*QKP + c4 + j] = hh;
            sQl[row*QKP + c4 + j] = __float2bfloat16_rn(vv[j] - __bfloat162float(hh));
        }
    }
    __syncthreads();

    // load Q fragments into registers (held for whole kernel)
    const int aRow = 16*warp + (lane & 7) + ((lane >> 3) & 1) * 8;
    const int aColSel = (lane >> 4) * 8;
    unsigned qh[3][4], ql[3][4];
    {
        const unsigned sQh_b = smem_addr(sQh), sQl_b = smem_addr(sQl);
        #pragma unroll
        for (int kk = 0; kk < 3; kk++) {
            unsigned off = (unsigned)((aRow*QKP + kk*16 + aColSel) * 2);
            ldsm_x4(qh[kk], sQh_b + off);
            ldsm_x4(ql[kk], sQl_b + off);
        }
    }

    float o[6][4];
    #pragma unroll
    for (int i = 0; i < 6; i++)
        #pragma unroll
        for (int j = 0; j < 4; j++) o[i][j] = 0.f;
    float m0r = -1e30f, m1r = -1e30f, l0 = 0.f, l1 = 0.f;

    const int row0 = q0 + 16*warp + (lane >> 2);
    const int row1 = row0 + 8;
    const bool rm0 = row0 < NM1, rm1 = row1 < NM1;

    const unsigned sKh_b = smem_addr(sKh), sKl_b = smem_addr(sKl);
    const unsigned sVh_b = smem_addr(sVh), sVl_b = smem_addr(sVl);
    const int bRowSel = (lane & 7) + ((lane >> 4) & 1) * 8;
    const int bColSel = ((lane >> 3) & 1) * 8;

    for (int kt = 0; kt < 17; kt++) {
        int k0 = kt * 64;
        if ((q0 + 63 < NM1) && (k0 >= NM1)) continue;

        __syncthreads();
        // stage K (split)
        #pragma unroll
        for (int i = 0; i < 6; i++) {
            int idx = tid + i*128;
            int row = idx / 12, c4 = (idx % 12) * 4;
            int kg = k0 + row;
            float4 v = make_float4(0.f,0.f,0.f,0.f);
            if (kg < SS) v = *(const float4*)(QKV + baseK + (size_t)kg*QKVN + c4);
            float vv[4] = {v.x, v.y, v.z, v.w};
            #pragma unroll
            for (int j = 0; j < 4; j++) {
                __nv_bfloat16 hh = __float2bfloat16_rn(vv[j]);
                sKh[row*QKP + c4 + j] = hh;
                sKl[row*QKP + c4 + j] = __float2bfloat16_rn(vv[j] - __bfloat162float(hh));
            }
        }
        // stage V transposed (split): sV[dim][key]
        #pragma unroll
        for (int i = 0; i < 6; i++) {
            int idx = tid + i*128;
            int key = idx / 12, c4 = (idx % 12) * 4;
            int kg = k0 + key;
            float4 v = make_float4(0.f,0.f,0.f,0.f);
            if (kg < SS) v = *(const float4*)(QKV + baseV + (size_t)kg*QKVN + c4);
            float vv[4] = {v.x, v.y, v.z, v.w};
            #pragma unroll
            for (int j = 0; j < 4; j++) {
                __nv_bfloat16 hh = __float2bfloat16_rn(vv[j]);
                sVh[(c4 + j)*VTP + key] = hh;
                sVl[(c4 + j)*VTP + key] = __float2bfloat16_rn(vv[j] - __bfloat162float(hh));
            }
        }
        __syncthreads();

        // S = Q*K^T (3-term)
        float s[8][4];
        #pragma unroll
        for (int i = 0; i < 8; i++)
            #pragma unroll
            for (int j = 0; j < 4; j++) s[i][j] = 0.f;

        #pragma unroll
        for (int kk = 0; kk < 3; kk++) {
            unsigned bhf[8][2], blf[8][2];
            #pragma unroll
            for (int nb = 0; nb < 4; nb++) {
                unsigned off = (unsigned)(((nb*16 + bRowSel)*QKP + kk*16 + bColSel) * 2);
                unsigned t[4];
                ldsm_x4(t, sKh_b + off);
                bhf[2*nb][0]=t[0]; bhf[2*nb][1]=t[1]; bhf[2*nb+1][0]=t[2]; bhf[2*nb+1][1]=t[3];
                ldsm_x4(t, sKl_b + off);
                blf[2*nb][0]=t[0]; blf[2*nb][1]=t[1]; blf[2*nb+1][0]=t[2]; blf[2*nb+1][1]=t[3];
            }
            #pragma unroll
            for (int nt = 0; nt < 8; nt++) {
                mma_bf16(s[nt], qh[kk], bhf[nt]);
                mma_bf16(s[nt], ql[kk], bhf[nt]);
                mma_bf16(s[nt], qh[kk], blf[nt]);
            }
        }

        // mask
        #pragma unroll
        for (int nt = 0; nt < 8; nt++) {
            #pragma unroll
            for (int e = 0; e < 2; e++) {
                int col = k0 + nt*8 + (lane & 3)*2 + e;
                bool cm = (col >= SS);
                bool cnm = (col >= NM1);
                if (cm || (rm0 && cnm)) s[nt][e]   = -1e30f;
                if (cm || (rm1 && cnm)) s[nt][2+e] = -1e30f;
            }
        }

        // online softmax
        float t0 = -1e30f, t1 = -1e30f;
        #pragma unroll
        for (int nt = 0; nt < 8; nt++) {
            t0 = fmaxf(t0, fmaxf(s[nt][0], s[nt][1]));
            t1 = fmaxf(t1, fmaxf(s[nt][2], s[nt][3]));
        }
        t0 = fmaxf(t0, __shfl_xor_sync(0xffffffffu, t0, 1));
        t0 = fmaxf(t0, __shfl_xor_sync(0xffffffffu, t0, 2));
        t1 = fmaxf(t1, __shfl_xor_sync(0xffffffffu, t1, 1));
        t1 = fmaxf(t1, __shfl_xor_sync(0xffffffffu, t1, 2));
        float nm0 = fmaxf(m0r, t0), nm1 = fmaxf(m1r, t1);
        float f0 = __expf(m0r - nm0), f1 = __expf(m1r - nm1);
        m0r = nm0; m1r = nm1;

        float ps0 = 0.f, ps1 = 0.f;
        #pragma unroll
        for (int nt = 0; nt < 8; nt++) {
            s[nt][0] = __expf(s[nt][0] - m0r);
            s[nt][1] = __expf(s[nt][1] - m0r);
            s[nt][2] = __expf(s[nt][2] - m1r);
            s[nt][3] = __expf(s[nt][3] - m1r);
            ps0 += s[nt][0] + s[nt][1];
            ps1 += s[nt][2] + s[nt][3];
        }
        ps0 += __shfl_xor_sync(0xffffffffu, ps0, 1);
        ps0 += __shfl_xor_sync(0xffffffffu, ps0, 2);
        ps1 += __shfl_xor_sync(0xffffffffu, ps1, 1);
        ps1 += __shfl_xor_sync(0xffffffffu, ps1, 2);
        l0 = l0*f0 + ps0;
        l1 = l1*f1 + ps1;
        #pragma unroll
        for (int nt = 0; nt < 6; nt++) {
            o[nt][0] *= f0; o[nt][1] *= f0;
            o[nt][2] *= f1; o[nt][3] *= f1;
        }

        // O += P*V (3-term). A-fragments built from S registers (C-layout == A-layout rows).
        #pragma unroll
        for (int kk = 0; kk < 4; kk++) {
            unsigned pah[4], pal[4];
            split2(s[2*kk  ][0], s[2*kk  ][1], pah[0], pal[0]);
            split2(s[2*kk  ][2], s[2*kk  ][3], pah[1], pal[1]);
            split2(s[2*kk+1][0], s[2*kk+1][1], pah[2], pal[2]);
            split2(s[2*kk+1][2], s[2*kk+1][3], pah[3], pal[3]);

            unsigned vbh[6][2], vbl[6][2];
            #pragma unroll
            for (int nb = 0; nb < 3; nb++) {
                unsigned off = (unsigned)(((nb*16 + bRowSel)*VTP + kk*16 + bColSel) * 2);
                unsigned t[4];
                ldsm_x4(t, sVh_b + off);
                vbh[2*nb][0]=t[0]; vbh[2*nb][1]=t[1]; vbh[2*nb+1][0]=t[2]; vbh[2*nb+1][1]=t[3];
                ldsm_x4(t, sVl_b + off);
                vbl[2*nb][0]=t[0]; vbl[2*nb][1]=t[1]; vbl[2*nb+1][0]=t[2]; vbl[2*nb+1][1]=t[3];
            }
            #pragma unroll
            for (int nt = 0; nt < 6; nt++) {
                mma_bf16(o[nt], pah, vbh[nt]);
                mma_bf16(o[nt], pal, vbh[nt]);
                mma_bf16(o[nt], pah, vbl[nt]);
            }
        }
    }

    // normalize + store as bf16 hi/lo
    float il0 = 1.f / l0, il1 = 1.f / l1;
    #pragma unroll
    for (int nt = 0; nt < 6; nt++) {
        int col = h*DH + nt*8 + (lane & 3)*2;
        if (row0 < SS) {
            unsigned hh, ll;
            split2(o[nt][0]*il0, o[nt][1]*il0, hh, ll);
            *(unsigned*)&AH[(size_t)(b*SS + row0)*DD + col] = hh;
            *(unsigned*)&AL[(size_t)(b*SS + row0)*DD + col] = ll;
        }
        if (row1 < SS) {
            unsigned hh, ll;
            split2(o[nt][2]*il1, o[nt][3]*il1, hh, ll);
            *(unsigned*)&AH[(size_t)(b*SS + row1)*DD + col] = hh;
            *(unsigned*)&AL[(size_t)(b*SS + row1)*DD + col] = ll;
        }
    }
}

// ---------------- residual add + layernorm (writes fp32 + bf16 hi/lo) ----------------
__global__ void __launch_bounds__(128) add_ln_kernel(float* __restrict__ src, const float* __restrict__ res,
                                                     const float* __restrict__ g, const float* __restrict__ bta,
                                                     __nv_bfloat16* __restrict__ XH, __nv_bfloat16* __restrict__ XL)
{
    int row = blockIdx.x;
    int tid = threadIdx.x;
    float x[3];
    float s = 0.f, sq = 0.f;
    #pragma unroll
    for (int i = 0; i < 3; i++) {
        int d = tid + i*128;
        float v = src[(size_t)row*DD + d] + res[(size_t)row*DD + d];
        x[i] = v; s += v; sq += v*v;
    }
    #pragma unroll
    for (int o = 16; o > 0; o >>= 1) {
        s  += __shfl_xor_sync(0xffffffffu, s,  o);
        sq += __shfl_xor_sync(0xffffffffu, sq, o);
    }
    __shared__ float ss[4], ssq[4];
    int w = tid >> 5;
    if ((tid & 31) == 0) { ss[w] = s; ssq[w] = sq; }
    __syncthreads();
    s  = ss[0]+ss[1]+ss[2]+ss[3];
    sq = ssq[0]+ssq[1]+ssq[2]+ssq[3];
    float mean = s * (1.f/384.f);
    float var  = sq * (1.f/384.f) - mean*mean;
    float rs = rsqrtf(var + 1e-5f);
    #pragma unroll
    for (int i = 0; i < 3; i++) {
        int d = tid + i*128;
        float y = (x[i]-mean)*rs*g[d] + bta[d];
        src[(size_t)row*DD + d] = y;
        __nv_bfloat16 hh = __float2bfloat16_rn(y);
        XH[(size_t)row*DD + d] = hh;
        XL[(size_t)row*DD + d] = __float2bfloat16_rn(y - __bfloat162float(hh));
    }
}

// ---------------- output slice ----------------
__global__ void copy_out_kernel(float* __restrict__ out)
{
    int idx = blockIdx.x*blockDim.x + threadIdx.x;
    if (idx >= BB*TT*DD) return;
    int d = idx % DD;
    int t = (idx/DD) % TT;
    int b = idx / (DD*TT);
    out[idx] = g_SRC[((size_t)(b*SS + (SS-TT) + t))*DD + d];
}

// ---------------- host launcher ----------------
extern "C" void kernel_launch(void* const* d_in, const int* in_sizes, int n_in,
                              void* d_out, int out_size)
{
    (void)in_sizes; (void)n_in; (void)out_size;
    const float* hand_t    = (const float*)d_in[0];
    const float* head_t    = (const float*)d_in[1];
    const float* hand_m1   = (const float*)d_in[2];
    const float* head_m1   = (const float*)d_in[3];
    const float* c_hand_t  = (const float*)d_in[4];
    const float* c_head_t  = (const float*)d_in[5];
    const float* c_hand_m1 = (const float*)d_in[6];
    const float* c_head_m1 = (const float*)d_in[7];
    const float* state_t   = (const float*)d_in[8];
    const float* state_m1  = (const float*)d_in[9];
    const float* tr_t      = (const float*)d_in[10];
    const float* tr_m1     = (const float*)d_in[11];
    const float* tok_m1    = (const float*)d_in[12];
    const float* tok_t     = (const float*)d_in[13];
    const float* Wq  = (const float*)d_in[14];
    const float* bq  = (const float*)d_in[15];
    const float* Wk  = (const float*)d_in[16];
    const float* bk  = (const float*)d_in[17];
    const float* Wv  = (const float*)d_in[18];
    const float* bv  = (const float*)d_in[19];
    const float* Wo  = (const float*)d_in[20];
    const float* bo  = (const float*)d_in[21];
    const float* W1  = (const float*)d_in[22];
    const float* b1  = (const float*)d_in[23];
    const float* W2  = (const float*)d_in[24];
    const float* b2  = (const float*)d_in[25];
    const float* g1  = (const float*)d_in[26];
    const float* be1 = (const float*)d_in[27];
    const float* g2  = (const float*)d_in[28];
    const float* be2 = (const float*)d_in[29];

    float *SRC, *QKVp, *PROJ, *BQKV;
    __nv_bfloat16 *XH, *XL, *FFH, *FFL, *WqkvH, *WqkvL, *WoH, *WoL, *W1H, *W1L, *W2H, *W2L;
    cudaGetSymbolAddress((void**)&SRC,   g_SRC);
    cudaGetSymbolAddress((void**)&QKVp,  g_QKV);
    cudaGetSymbolAddress((void**)&PROJ,  g_PROJ);
    cudaGetSymbolAddress((void**)&XH,    g_XH);
    cudaGetSymbolAddress((void**)&XL,    g_XL);
    cudaGetSymbolAddress((void**)&FFH,   g_FFH);
    cudaGetSymbolAddress((void**)&FFL,   g_FFL);
    cudaGetSymbolAddress((void**)&WqkvH, g_WqkvH);
    cudaGetSymbolAddress((void**)&WqkvL, g_WqkvL);
    cudaGetSymbolAddress((void**)&WoH,   g_WoH);
    cudaGetSymbolAddress((void**)&WoL,   g_WoL);
    cudaGetSymbolAddress((void**)&W1H,   g_W1H);
    cudaGetSymbolAddress((void**)&W1L,   g_W1L);
    cudaGetSymbolAddress((void**)&W2H,   g_W2H);
    cudaGetSymbolAddress((void**)&W2L,   g_W2L);
    cudaGetSymbolAddress((void**)&BQKV,  g_bqkv);

    build_src_kernel<<<1024, 256>>>(hand_t, head_t, hand_m1, head_m1,
                                    state_t, state_m1, tok_m1, tok_t);
    build_coord_kernel<<<98, 256>>>(c_hand_t, c_head_t, c_hand_m1, c_head_m1, tr_t, tr_m1);

    // split / pack all weights once
    split_qkv_w_kernel<<<2048, 256>>>(Wq, Wk, Wv);
    pack_qkv_b_kernel<<<(LL*QKVN + 255)/256, 256>>>(bq, bk, bv);
    split_kernel<<<2048, 256>>>(Wo, WoH, WoL, LL*DD*DD);
    split_kernel<<<2048, 256>>>(W1, W1H, W1L, LL*FFD*DD);
    split_kernel<<<2048, 256>>>(W2, W2H, W2L, LL*DD*FFD);

    // initial activation split
    split_kernel<<<2048, 256>>>(SRC, XH, XL, MM*DD);

    const int MB = (MM + 127)/128;   // 65
    for (int l = 0; l < LL; l++) {
        gemm_kernel<false,false><<<dim3(MB, QKVN/128), 256>>>(MM, QKVN, DD, XH, XL,
            WqkvH + (size_t)l*QKVN*DD, WqkvL + (size_t)l*QKVN*DD, BQKV + l*QKVN, QKVp, nullptr, nullptr);
        rope_kernel<<<(BB*SS*HH + 255)/256, 256>>>();
        attn_mma_kernel<<<dim3(17, 64), 128>>>(QKVp, XH, XL);   // attn out -> split bufs
        gemm_kernel<false,false><<<dim3(MB, DD/128), 256>>>(MM, DD, DD, XH, XL,
            WoH + (size_t)l*DD*DD, WoL + (size_t)l*DD*DD, bo + l*DD, PROJ, nullptr, nullptr);
        add_ln_kernel<<<MM, 128>>>(SRC, PROJ, g1 + l*DD, be1 + l*DD, XH, XL);
        gemm_kernel<true,true><<<dim3(MB, FFD/128), 256>>>(MM, FFD, DD, XH, XL,
            W1H + (size_t)l*FFD*DD, W1L + (size_t)l*FFD*DD, b1 + l*FFD, nullptr, FFH, FFL);
        gemm_kernel<false,false><<<dim3(MB, DD/128), 256>>>(MM, DD, FFD, FFH, FFL,
            W2H + (size_t)l*DD*FFD, W2L + (size_t)l*DD*FFD, b2 + l*DD, PROJ, nullptr, nullptr);
        add_ln_kernel<<<MM, 128>>>(SRC, PROJ, g2 + l*DD, be2 + l*DD, XH, XL);
    }
    copy_out_kernel<<<48, 256>>>((float*)d_out);
}

// round 4
// speedup vs baseline: 2.8003x; 1.1459x over previous
#include <cuda_runtime.h>
#include <cuda_bf16.h>
#include <math.h>

// Problem constants
#define BB 8
#define NN 256
#define DD 384
#define LL 6
#define HH 8
#define FFD 1536
#define TT 4
#define DH 48
#define NM1 517
#define SS 1034
#define SPAD 1088
#define MM (BB*SS)   // 8272
#define QKVN 1152    // 3*DD

// ---------------- scratch (static device globals; no allocation) ----------------
__device__ float g_SRC [MM*DD];
__device__ float g_COORD[MM*3];
__device__ float g_QKV [MM*QKVN];
__device__ float g_PROJ[MM*DD];

__device__ __nv_bfloat16 g_XH[MM*DD];
__device__ __nv_bfloat16 g_XL[MM*DD];
__device__ __nv_bfloat16 g_FFH[MM*FFD];
__device__ __nv_bfloat16 g_FFL[MM*FFD];

// attention operand arrays (pre-split, padded to SPAD rows)
__device__ __nv_bfloat16 g_QH[64*SPAD*DH];
__device__ __nv_bfloat16 g_QL[64*SPAD*DH];
__device__ __nv_bfloat16 g_KH[64*SPAD*DH];
__device__ __nv_bfloat16 g_KL[64*SPAD*DH];
__device__ __nv_bfloat16 g_VH[64*DH*SPAD];
__device__ __nv_bfloat16 g_VL[64*DH*SPAD];

__device__ __nv_bfloat16 g_WqkvH[LL*QKVN*DD];
__device__ __nv_bfloat16 g_WqkvL[LL*QKVN*DD];
__device__ __nv_bfloat16 g_WoH[LL*DD*DD];
__device__ __nv_bfloat16 g_WoL[LL*DD*DD];
__device__ __nv_bfloat16 g_W1H[LL*FFD*DD];
__device__ __nv_bfloat16 g_W1L[LL*FFD*DD];
__device__ __nv_bfloat16 g_W2H[LL*DD*FFD];
__device__ __nv_bfloat16 g_W2L[LL*DD*FFD];
__device__ float g_bqkv[LL*QKVN];

// ---------------- input assembly ----------------
__global__ void build_src_kernel(const float* __restrict__ hand_t, const float* __restrict__ head_t,
                                 const float* __restrict__ hand_m1, const float* __restrict__ head_m1,
                                 const float* __restrict__ state_t, const float* __restrict__ state_m1,
                                 const float* __restrict__ tok_m1, const float* __restrict__ tok_t)
{
    for (int idx = blockIdx.x*blockDim.x + threadIdx.x; idx < BB*SS*DD; idx += gridDim.x*blockDim.x) {
        int d = idx % DD;
        int s = (idx / DD) % SS;
        int b = idx / (DD*SS);
        float v;
        if      (s == 0)    v = state_m1[b*DD + d];
        else if (s < 257)   v = hand_m1[((b*NN)+(s-1  ))*DD + d];
        else if (s < 513)   v = head_m1[((b*NN)+(s-257))*DD + d];
        else if (s < 517)   v = tok_m1[(s-513)*DD + d];
        else if (s == 517)  v = state_t[b*DD + d];
        else if (s < 774)   v = hand_t[((b*NN)+(s-518))*DD + d];
        else if (s < 1030)  v = head_t[((b*NN)+(s-774))*DD + d];
        else                v = tok_t[(s-1030)*DD + d];
        g_SRC[idx] = v;
    }
}

__global__ void build_coord_kernel(const float* __restrict__ c_hand_t, const float* __restrict__ c_head_t,
                                   const float* __restrict__ c_hand_m1, const float* __restrict__ c_head_m1,
                                   const float* __restrict__ tr_t, const float* __restrict__ tr_m1)
{
    for (int idx = blockIdx.x*blockDim.x + threadIdx.x; idx < BB*SS*3; idx += gridDim.x*blockDim.x) {
        int cdim = idx % 3;
        int s = (idx/3) % SS;
        int b = idx / (3*SS);
        float v;
        if      (s == 0)    v = tr_m1[b*3+cdim];
        else if (s < 257)   v = c_hand_m1[((b*NN)+(s-1  ))*3 + cdim];
        else if (s < 513)   v = c_head_m1[((b*NN)+(s-257))*3 + cdim];
        else if (s < 517)   v = tr_m1[b*3+cdim];
        else if (s == 517)  v = tr_t[b*3+cdim];
        else if (s < 774)   v = c_hand_t[((b*NN)+(s-518))*3 + cdim];
        else if (s < 1030)  v = c_head_t[((b*NN)+(s-774))*3 + cdim];
        else                v = tr_t[b*3+cdim];
        g_COORD[idx] = v;
    }
}

// ---------------- fp32 -> (bf16 hi, bf16 lo) split ----------------
__global__ void split_kernel(const float* __restrict__ x,
                             __nv_bfloat16* __restrict__ hi,
                             __nv_bfloat16* __restrict__ lo, int n)
{
    for (int i = blockIdx.x*blockDim.x + threadIdx.x; i < n; i += gridDim.x*blockDim.x) {
        float v = x[i];
        __nv_bfloat16 h = __float2bfloat16_rn(v);
        float r = v - __bfloat162float(h);
        hi[i] = h;
        lo[i] = __float2bfloat16_rn(r);
    }
}

// pack Wq/Wk/Wv into [L][1152][384] and split
__global__ void split_qkv_w_kernel(const float* __restrict__ Wq, const float* __restrict__ Wk,
                                   const float* __restrict__ Wv)
{
    const int total = LL*QKVN*DD;
    for (int idx = blockIdx.x*blockDim.x + threadIdx.x; idx < total; idx += gridDim.x*blockDim.x) {
        int k = idx % DD;
        int r = (idx / DD) % QKVN;
        int l = idx / (DD*QKVN);
        float v;
        if      (r < DD)    v = Wq[((size_t)l*DD + r      )*DD + k];
        else if (r < 2*DD)  v = Wk[((size_t)l*DD + r-DD   )*DD + k];
        else                v = Wv[((size_t)l*DD + r-2*DD )*DD + k];
        __nv_bfloat16 h = __float2bfloat16_rn(v);
        g_WqkvH[idx] = h;
        g_WqkvL[idx] = __float2bfloat16_rn(v - __bfloat162float(h));
    }
}

__global__ void pack_qkv_b_kernel(const float* __restrict__ bq, const float* __restrict__ bk,
                                  const float* __restrict__ bv)
{
    int idx = blockIdx.x*blockDim.x + threadIdx.x;
    if (idx >= LL*QKVN) return;
    int r = idx % QKVN;
    int l = idx / QKVN;
    float v;
    if      (r < DD)   v = bq[l*DD + r];
    else if (r < 2*DD) v = bk[l*DD + r-DD];
    else               v = bv[l*DD + r-2*DD];
    g_bqkv[idx] = v;
}

// ---------------- mma / async helpers ----------------
__device__ __forceinline__ unsigned smem_addr(const void* p) {
    return (unsigned)__cvta_generic_to_shared(p);
}
__device__ __forceinline__ void ldsm_x4(unsigned r[4], unsigned addr) {
    asm volatile("ldmatrix.sync.aligned.m8n8.x4.shared.b16 {%0,%1,%2,%3}, [%4];"
                 : "=r"(r[0]), "=r"(r[1]), "=r"(r[2]), "=r"(r[3]) : "r"(addr));
}
__device__ __forceinline__ void mma_bf16(float c[4], const unsigned a[4], const unsigned b[2]) {
    asm volatile("mma.sync.aligned.m16n8k16.row.col.f32.bf16.bf16.f32 "
                 "{%0,%1,%2,%3}, {%4,%5,%6,%7}, {%8,%9}, {%0,%1,%2,%3};"
                 : "+f"(c[0]), "+f"(c[1]), "+f"(c[2]), "+f"(c[3])
                 : "r"(a[0]), "r"(a[1]), "r"(a[2]), "r"(a[3]), "r"(b[0]), "r"(b[1]));
}
__device__ __forceinline__ void cpa16(unsigned dst, const void* src, bool pred) {
    int sz = pred ? 16 : 0;
    asm volatile("cp.async.cg.shared.global [%0], [%1], 16, %2;"
                 :: "r"(dst), "l"(src), "r"(sz) : "memory");
}
#define CP_COMMIT() asm volatile("cp.async.commit_group;" ::: "memory")
#define CP_WAIT1()  asm volatile("cp.async.wait_group 1;" ::: "memory")
#define CP_WAIT0()  asm volatile("cp.async.wait_group 0;" ::: "memory")

// pack two fp32 into bf16x2 hi + residual bf16x2 lo
__device__ __forceinline__ void split2(float a, float b, unsigned &h, unsigned &l) {
    __nv_bfloat162 hh = __floats2bfloat162_rn(a, b);
    h = *(unsigned*)&hh;
    float ra = a - __bfloat162float(hh.x);
    float rb = b - __bfloat162float(hh.y);
    __nv_bfloat162 ll = __floats2bfloat162_rn(ra, rb);
    l = *(unsigned*)&ll;
}

// ---------------- bf16x3 tensor-core GEMM, 2-stage cp.async pipeline ----------------
#define LDSMP 40                         // padded smem row stride (bf16)
#define GARR (128*LDSMP)                 // elems per operand array
#define GARRB (GARR*2)                   // bytes
#define GSMEM (2*4*GARRB)                // total dynamic smem bytes (81920)

template<bool DO_GELU, bool SPLIT_OUT>
__global__ void __launch_bounds__(256) gemm_kernel(int M, int N, int K,
    const __nv_bfloat16* __restrict__ Ah, const __nv_bfloat16* __restrict__ Al,
    const __nv_bfloat16* __restrict__ Wh, const __nv_bfloat16* __restrict__ Wl,
    const float* __restrict__ bias, float* __restrict__ C,
    __nv_bfloat16* __restrict__ Ch, __nv_bfloat16* __restrict__ Cl)
{
    extern __shared__ __nv_bfloat16 dsm[];
    const int tid  = threadIdx.x;
    const int lane = tid & 31;
    const int warp = tid >> 5;
    const int wm   = warp >> 2;
    const int wn   = warp & 3;
    const int m0   = blockIdx.x * 128;
    const int n0   = blockIdx.y * 128;

    float c[4][4][4];
    #pragma unroll
    for (int i = 0; i < 4; i++)
        #pragma unroll
        for (int j = 0; j < 4; j++)
            #pragma unroll
            for (int r = 0; r < 4; r++) c[i][j][r] = 0.f;

    const int lr = tid >> 2;
    const int lc = (tid & 3) * 8;

    const int aRow    = wm*64 + (lane & 7) + ((lane >> 3) & 1) * 8;
    const int aColSel = (lane >> 4) * 8;
    const int bRow    = wn*32 + (lane & 7) + ((lane >> 4) & 1) * 8;
    const int bColSel = ((lane >> 3) & 1) * 8;

    const unsigned sbase = smem_addr(dsm);

    auto load_tile = [&](int kt, int stage) {
        const int kc = kt * 32;
        const unsigned sb = sbase + stage*4*GARRB;
        #pragma unroll
        for (int half = 0; half < 2; half++) {
            int r  = lr + half*64;
            int gm = m0 + r;
            bool pa = gm < M;
            int gmc = pa ? gm : 0;
            unsigned drow = (unsigned)((r*LDSMP + lc) * 2);
            cpa16(sb + drow,           Ah + (size_t)gmc*K + kc + lc, pa);
            cpa16(sb + GARRB + drow,   Al + (size_t)gmc*K + kc + lc, pa);
            cpa16(sb + 2*GARRB + drow, Wh + (size_t)(n0 + r)*K + kc + lc, true);
            cpa16(sb + 3*GARRB + drow, Wl + (size_t)(n0 + r)*K + kc + lc, true);
        }
    };

    const int nk = K >> 5;
    load_tile(0, 0);
    CP_COMMIT();

    for (int kt = 0; kt < nk; kt++) {
        const int cur = kt & 1;
        if (kt + 1 < nk) load_tile(kt + 1, cur ^ 1);
        CP_COMMIT();
        CP_WAIT1();
        __syncthreads();

        const unsigned sb    = sbase + cur*4*GARRB;
        const unsigned sAh_b = sb;
        const unsigned sAl_b = sb + GARRB;
        const unsigned sBh_b = sb + 2*GARRB;
        const unsigned sBl_b = sb + 3*GARRB;

        #pragma unroll
        for (int kk = 0; kk < 2; kk++) {
            unsigned ah[4][4], al[4][4], bh[4][2], bl[4][2];
            #pragma unroll
            for (int mt = 0; mt < 4; mt++) {
                unsigned off = (unsigned)(((aRow + mt*16)*LDSMP + kk*16 + aColSel) * 2);
                ldsm_x4(ah[mt], sAh_b + off);
                ldsm_x4(al[mt], sAl_b + off);
            }
            #pragma unroll
            for (int np = 0; np < 2; np++) {
                unsigned off = (unsigned)(((bRow + np*16)*LDSMP + kk*16 + bColSel) * 2);
                unsigned t[4];
                ldsm_x4(t, sBh_b + off);
                bh[2*np][0]=t[0]; bh[2*np][1]=t[1]; bh[2*np+1][0]=t[2]; bh[2*np+1][1]=t[3];
                ldsm_x4(t, sBl_b + off);
                bl[2*np][0]=t[0]; bl[2*np][1]=t[1]; bl[2*np+1][0]=t[2]; bl[2*np+1][1]=t[3];
            }
            #pragma unroll
            for (int mt = 0; mt < 4; mt++)
                #pragma unroll
                for (int nt = 0; nt < 4; nt++) {
                    mma_bf16(c[mt][nt], ah[mt], bh[nt]);
                    mma_bf16(c[mt][nt], al[mt], bh[nt]);
                    mma_bf16(c[mt][nt], ah[mt], bl[nt]);
                }
        }
        __syncthreads();
    }

    #pragma unroll
    for (int mt = 0; mt < 4; mt++) {
        #pragma unroll
        for (int nt = 0; nt < 4; nt++) {
            int col  = n0 + wn*32 + nt*8 + (lane & 3)*2;
            float b0 = bias[col], b1 = bias[col+1];
            int row0 = m0 + wm*64 + mt*16 + (lane >> 2);
            int row1 = row0 + 8;
            float v0 = c[mt][nt][0] + b0, v1 = c[mt][nt][1] + b1;
            float v2 = c[mt][nt][2] + b0, v3 = c[mt][nt][3] + b1;
            if (DO_GELU) {
                v0 = 0.5f*v0*(1.0f+erff(v0*0.7071067811865475f));
                v1 = 0.5f*v1*(1.0f+erff(v1*0.7071067811865475f));
                v2 = 0.5f*v2*(1.0f+erff(v2*0.7071067811865475f));
                v3 = 0.5f*v3*(1.0f+erff(v3*0.7071067811865475f));
            }
            if (SPLIT_OUT) {
                unsigned h01, l01, h23, l23;
                split2(v0, v1, h01, l01);
                split2(v2, v3, h23, l23);
                if (row0 < M) { *(unsigned*)&Ch[(size_t)row0*N + col] = h01;
                                *(unsigned*)&Cl[(size_t)row0*N + col] = l01; }
                if (row1 < M) { *(unsigned*)&Ch[(size_t)row1*N + col] = h23;
                                *(unsigned*)&Cl[(size_t)row1*N + col] = l23; }
            } else {
                if (row0 < M) *(float2*)&C[(size_t)row0*N + col] = make_float2(v0, v1);
                if (row1 < M) *(float2*)&C[(size_t)row1*N + col] = make_float2(v2, v3);
            }
        }
    }
}

// ---------------- rope + split + relayout for attention ----------------
// reads fp32 packed QKV, writes: QH/QL,KH/KL [bh][s][48] (Q pre-scaled), VH/VL [bh][48][s]
__global__ void __launch_bounds__(256) rope_split_kernel()
{
    int t = blockIdx.x*blockDim.x + threadIdx.x;
    if (t >= 64*SS) return;
    int s  = t % SS;
    int bh = t / SS;
    int b = bh >> 3, h = bh & 7;

    const float* src = g_QKV + ((size_t)(b*SS + s))*QKVN + h*DH;
    float q[48], k[48], v[48];
    #pragma unroll
    for (int i = 0; i < 12; i++) {
        *(float4*)&q[i*4] = *(const float4*)(src + i*4);
        *(float4*)&k[i*4] = *(const float4*)(src + DD + i*4);
        *(float4*)&v[i*4] = *(const float4*)(src + 2*DD + i*4);
    }

    float invf[8];
    #pragma unroll
    for (int j = 0; j < 8; j++)
        invf[j] = exp2f(-1.6609640474436813f * (float)j);

    #pragma unroll
    for (int a = 0; a < 3; a++) {
        float co = g_COORD[(b*SS + s)*3 + a];
        #pragma unroll
        for (int j = 0; j < 8; j++) {
            float ang = co * invf[j];
            float cs = cosf(ang), sn = sinf(ang);
            int i1 = a*16 + j, i2 = i1 + 8;
            float q1 = q[i1], q2 = q[i2];
            q[i1] = q1*cs - q2*sn;  q[i2] = q1*sn + q2*cs;
            float k1 = k[i1], k2 = k[i2];
            k[i1] = k1*cs - k2*sn;  k[i2] = k1*sn + k2*cs;
        }
    }

    const float scale = 0.14433756729740643f; // 1/sqrt(48)
    size_t qkbase = ((size_t)bh*SPAD + s)*DH;
    #pragma unroll
    for (int d = 0; d < 48; d++) {
        float qq = q[d]*scale;
        __nv_bfloat16 hh = __float2bfloat16_rn(qq);
        g_QH[qkbase + d] = hh;
        g_QL[qkbase + d] = __float2bfloat16_rn(qq - __bfloat162float(hh));
        hh = __float2bfloat16_rn(k[d]);
        g_KH[qkbase + d] = hh;
        g_KL[qkbase + d] = __float2bfloat16_rn(k[d] - __bfloat162float(hh));
        hh = __float2bfloat16_rn(v[d]);
        size_t vi = ((size_t)bh*DH + d)*SPAD + s;
        g_VH[vi] = hh;
        g_VL[vi] = __float2bfloat16_rn(v[d] - __bfloat162float(hh));
    }
}

// ---------------- tensor-core flash attention ----------------
#define QKP 56
#define VTP 72

__global__ void __launch_bounds__(128) attn_mma_kernel(__nv_bfloat16* __restrict__ AH,
                                                       __nv_bfloat16* __restrict__ AL)
{
    const int bh = blockIdx.y;
    const int b = bh >> 3, h = bh & 7;
    const int q0 = blockIdx.x * 64;
    const int tid = threadIdx.x;
    const int lane = tid & 31;
    const int warp = tid >> 5;

    __shared__ __nv_bfloat16 sQh[64*QKP], sQl[64*QKP];
    __shared__ __nv_bfloat16 sKh[64*QKP], sKl[64*QKP];
    __shared__ __nv_bfloat16 sVh[48*VTP], sVl[48*VTP];

    const unsigned sQh_b = smem_addr(sQh), sQl_b = smem_addr(sQl);
    const unsigned sKh_b = smem_addr(sKh), sKl_b = smem_addr(sKl);
    const unsigned sVh_b = smem_addr(sVh), sVl_b = smem_addr(sVl);

    const size_t qkBase = (size_t)bh*SPAD*DH;
    const size_t vBase  = (size_t)bh*DH*SPAD;

    // stage Q via cp.async (rows q0..q0+63, 48 elems per row = 6x16B chunks)
    #pragma unroll
    for (int i = 0; i < 3; i++) {
        int cidx = tid + i*128;
        int row = cidx / 6, off = (cidx % 6) * 8;
        unsigned d = (unsigned)((row*QKP + off) * 2);
        const size_t g = qkBase + (size_t)(q0 + row)*DH + off;
        cpa16(sQh_b + d, g_QH + g, true);
        cpa16(sQl_b + d, g_QL + g, true);
    }
    CP_COMMIT(); CP_WAIT0();
    __syncthreads();

    const int aRow = 16*warp + (lane & 7) + ((lane >> 3) & 1) * 8;
    const int aColSel = (lane >> 4) * 8;
    unsigned qh[3][4], ql[3][4];
    #pragma unroll
    for (int kk = 0; kk < 3; kk++) {
        unsigned off = (unsigned)((aRow*QKP + kk*16 + aColSel) * 2);
        ldsm_x4(qh[kk], sQh_b + off);
        ldsm_x4(ql[kk], sQl_b + off);
    }

    float o[6][4];
    #pragma unroll
    for (int i = 0; i < 6; i++)
        #pragma unroll
        for (int j = 0; j < 4; j++) o[i][j] = 0.f;
    float m0r = -1e30f, m1r = -1e30f, l0 = 0.f, l1 = 0.f;

    const int row0 = q0 + 16*warp + (lane >> 2);
    const int row1 = row0 + 8;
    const bool rm0 = row0 < NM1, rm1 = row1 < NM1;

    const int bRowSel = (lane & 7) + ((lane >> 4) & 1) * 8;
    const int bColSel = ((lane >> 3) & 1) * 8;

    for (int kt = 0; kt < 17; kt++) {
        int k0 = kt * 64;
        if ((q0 + 63 < NM1) && (k0 >= NM1)) continue;

        __syncthreads();
        // stage K (64 rows x 6 chunks) and Vt (48 rows x 8 chunks) via cp.async
        #pragma unroll
        for (int i = 0; i < 3; i++) {
            int cidx = tid + i*128;
            int row = cidx / 6, off = (cidx % 6) * 8;
            unsigned d = (unsigned)((row*QKP + off) * 2);
            const size_t g = qkBase + (size_t)(k0 + row)*DH + off;
            cpa16(sKh_b + d, g_KH + g, true);
            cpa16(sKl_b + d, g_KL + g, true);
        }
        #pragma unroll
        for (int i = 0; i < 3; i++) {
            int cidx = tid + i*128;
            int row = cidx / 8, off = (cidx % 8) * 8;
            unsigned d = (unsigned)((row*VTP + off) * 2);
            const size_t g = vBase + (size_t)row*SPAD + k0 + off;
            cpa16(sVh_b + d, g_VH + g, true);
            cpa16(sVl_b + d, g_VL + g, true);
        }
        CP_COMMIT(); CP_WAIT0();
        __syncthreads();

        // S = Q*K^T (3-term)
        float s[8][4];
        #pragma unroll
        for (int i = 0; i < 8; i++)
            #pragma unroll
            for (int j = 0; j < 4; j++) s[i][j] = 0.f;

        #pragma unroll
        for (int kk = 0; kk < 3; kk++) {
            unsigned bhf[8][2], blf[8][2];
            #pragma unroll
            for (int nb = 0; nb < 4; nb++) {
                unsigned off = (unsigned)(((nb*16 + bRowSel)*QKP + kk*16 + bColSel) * 2);
                unsigned t[4];
                ldsm_x4(t, sKh_b + off);
                bhf[2*nb][0]=t[0]; bhf[2*nb][1]=t[1]; bhf[2*nb+1][0]=t[2]; bhf[2*nb+1][1]=t[3];
                ldsm_x4(t, sKl_b + off);
                blf[2*nb][0]=t[0]; blf[2*nb][1]=t[1]; blf[2*nb+1][0]=t[2]; blf[2*nb+1][1]=t[3];
            }
            #pragma unroll
            for (int nt = 0; nt < 8; nt++) {
                mma_bf16(s[nt], qh[kk], bhf[nt]);
                mma_bf16(s[nt], ql[kk], bhf[nt]);
                mma_bf16(s[nt], qh[kk], blf[nt]);
            }
        }

        // mask
        #pragma unroll
        for (int nt = 0; nt < 8; nt++) {
            #pragma unroll
            for (int e = 0; e < 2; e++) {
                int col = k0 + nt*8 + (lane & 3)*2 + e;
                bool cm = (col >= SS);
                bool cnm = (col >= NM1);
                if (cm || (rm0 && cnm)) s[nt][e]   = -1e30f;
                if (cm || (rm1 && cnm)) s[nt][2+e] = -1e30f;
            }
        }

        // online softmax
        float t0 = -1e30f, t1 = -1e30f;
        #pragma unroll
        for (int nt = 0; nt < 8; nt++) {
            t0 = fmaxf(t0, fmaxf(s[nt][0], s[nt][1]));
            t1 = fmaxf(t1, fmaxf(s[nt][2], s[nt][3]));
        }
        t0 = fmaxf(t0, __shfl_xor_sync(0xffffffffu, t0, 1));
        t0 = fmaxf(t0, __shfl_xor_sync(0xffffffffu, t0, 2));
        t1 = fmaxf(t1, __shfl_xor_sync(0xffffffffu, t1, 1));
        t1 = fmaxf(t1, __shfl_xor_sync(0xffffffffu, t1, 2));
        float nm0 = fmaxf(m0r, t0), nm1 = fmaxf(m1r, t1);
        float f0 = __expf(m0r - nm0), f1 = __expf(m1r - nm1);
        m0r = nm0; m1r = nm1;

        float ps0 = 0.f, ps1 = 0.f;
        #pragma unroll
        for (int nt = 0; nt < 8; nt++) {
            s[nt][0] = __expf(s[nt][0] - m0r);
            s[nt][1] = __expf(s[nt][1] - m0r);
            s[nt][2] = __expf(s[nt][2] - m1r);
            s[nt][3] = __expf(s[nt][3] - m1r);
            ps0 += s[nt][0] + s[nt][1];
            ps1 += s[nt][2] + s[nt][3];
        }
        ps0 += __shfl_xor_sync(0xffffffffu, ps0, 1);
        ps0 += __shfl_xor_sync(0xffffffffu, ps0, 2);
        ps1 += __shfl_xor_sync(0xffffffffu, ps1, 1);
        ps1 += __shfl_xor_sync(0xffffffffu, ps1, 2);
        l0 = l0*f0 + ps0;
        l1 = l1*f1 + ps1;
        #pragma unroll
        for (int nt = 0; nt < 6; nt++) {
            o[nt][0] *= f0; o[nt][1] *= f0;
            o[nt][2] *= f1; o[nt][3] *= f1;
        }

        // O += P*V (3-term)
        #pragma unroll
        for (int kk = 0; kk < 4; kk++) {
            unsigned pah[4], pal[4];
            split2(s[2*kk  ][0], s[2*kk  ][1], pah[0], pal[0]);
            split2(s[2*kk  ][2], s[2*kk  ][3], pah[1], pal[1]);
            split2(s[2*kk+1][0], s[2*kk+1][1], pah[2], pal[2]);
            split2(s[2*kk+1][2], s[2*kk+1][3], pah[3], pal[3]);

            unsigned vbh[6][2], vbl[6][2];
            #pragma unroll
            for (int nb = 0; nb < 3; nb++) {
                unsigned off = (unsigned)(((nb*16 + bRowSel)*VTP + kk*16 + bColSel) * 2);
                unsigned t[4];
                ldsm_x4(t, sVh_b + off);
                vbh[2*nb][0]=t[0]; vbh[2*nb][1]=t[1]; vbh[2*nb+1][0]=t[2]; vbh[2*nb+1][1]=t[3];
                ldsm_x4(t, sVl_b + off);
                vbl[2*nb][0]=t[0]; vbl[2*nb][1]=t[1]; vbl[2*nb+1][0]=t[2]; vbl[2*nb+1][1]=t[3];
            }
            #pragma unroll
            for (int nt = 0; nt < 6; nt++) {
                mma_bf16(o[nt], pah, vbh[nt]);
                mma_bf16(o[nt], pal, vbh[nt]);
                mma_bf16(o[nt], pah, vbl[nt]);
            }
        }
    }

    // normalize + store as bf16 hi/lo
    float il0 = 1.f / l0, il1 = 1.f / l1;
    #pragma unroll
    for (int nt = 0; nt < 6; nt++) {
        int col = h*DH + nt*8 + (lane & 3)*2;
        if (row0 < SS) {
            unsigned hh, ll;
            split2(o[nt][0]*il0, o[nt][1]*il0, hh, ll);
            *(unsigned*)&AH[(size_t)(b*SS + row0)*DD + col] = hh;
            *(unsigned*)&AL[(size_t)(b*SS + row0)*DD + col] = ll;
        }
        if (row1 < SS) {
            unsigned hh, ll;
            split2(o[nt][2]*il1, o[nt][3]*il1, hh, ll);
            *(unsigned*)&AH[(size_t)(b*SS + row1)*DD + col] = hh;
            *(unsigned*)&AL[(size_t)(b*SS + row1)*DD + col] = ll;
        }
    }
}

// ---------------- residual add + layernorm (writes fp32 + bf16 hi/lo) ----------------
__global__ void __launch_bounds__(128) add_ln_kernel(float* __restrict__ src, const float* __restrict__ res,
                                                     const float* __restrict__ g, const float* __restrict__ bta,
                                                     __nv_bfloat16* __restrict__ XH, __nv_bfloat16* __restrict__ XL)
{
    int row = blockIdx.x;
    int tid = threadIdx.x;
    float x[3];
    float s = 0.f, sq = 0.f;
    #pragma unroll
    for (int i = 0; i < 3; i++) {
        int d = tid + i*128;
        float v = src[(size_t)row*DD + d] + res[(size_t)row*DD + d];
        x[i] = v; s += v; sq += v*v;
    }
    #pragma unroll
    for (int o = 16; o > 0; o >>= 1) {
        s  += __shfl_xor_sync(0xffffffffu, s,  o);
        sq += __shfl_xor_sync(0xffffffffu, sq, o);
    }
    __shared__ float ss[4], ssq[4];
    int w = tid >> 5;
    if ((tid & 31) == 0) { ss[w] = s; ssq[w] = sq; }
    __syncthreads();
    s  = ss[0]+ss[1]+ss[2]+ss[3];
    sq = ssq[0]+ssq[1]+ssq[2]+ssq[3];
    float mean = s * (1.f/384.f);
    float var  = sq * (1.f/384.f) - mean*mean;
    float rs = rsqrtf(var + 1e-5f);
    #pragma unroll
    for (int i = 0; i < 3; i++) {
        int d = tid + i*128;
        float y = (x[i]-mean)*rs*g[d] + bta[d];
        src[(size_t)row*DD + d] = y;
        __nv_bfloat16 hh = __float2bfloat16_rn(y);
        XH[(size_t)row*DD + d] = hh;
        XL[(size_t)row*DD + d] = __float2bfloat16_rn(y - __bfloat162float(hh));
    }
}

// ---------------- output slice ----------------
__global__ void copy_out_kernel(float* __restrict__ out)
{
    int idx = blockIdx.x*blockDim.x + threadIdx.x;
    if (idx >= BB*TT*DD) return;
    int d = idx % DD;
    int t = (idx/DD) % TT;
    int b = idx / (DD*TT);
    out[idx] = g_SRC[((size_t)(b*SS + (SS-TT) + t))*DD + d];
}

// ---------------- host launcher ----------------
extern "C" void kernel_launch(void* const* d_in, const int* in_sizes, int n_in,
                              void* d_out, int out_size)
{
    (void)in_sizes; (void)n_in; (void)out_size;
    const float* hand_t    = (const float*)d_in[0];
    const float* head_t    = (const float*)d_in[1];
    const float* hand_m1   = (const float*)d_in[2];
    const float* head_m1   = (const float*)d_in[3];
    const float* c_hand_t  = (const float*)d_in[4];
    const float* c_head_t  = (const float*)d_in[5];
    const float* c_hand_m1 = (const float*)d_in[6];
    const float* c_head_m1 = (const float*)d_in[7];
    const float* state_t   = (const float*)d_in[8];
    const float* state_m1  = (const float*)d_in[9];
    const float* tr_t      = (const float*)d_in[10];
    const float* tr_m1     = (const float*)d_in[11];
    const float* tok_m1    = (const float*)d_in[12];
    const float* tok_t     = (const float*)d_in[13];
    const float* Wq  = (const float*)d_in[14];
    const float* bq  = (const float*)d_in[15];
    const float* Wk  = (const float*)d_in[16];
    const float* bk  = (const float*)d_in[17];
    const float* Wv  = (const float*)d_in[18];
    const float* bv  = (const float*)d_in[19];
    const float* Wo  = (const float*)d_in[20];
    const float* bo  = (const float*)d_in[21];
    const float* W1  = (const float*)d_in[22];
    const float* b1  = (const float*)d_in[23];
    const float* W2  = (const float*)d_in[24];
    const float* b2  = (const float*)d_in[25];
    const float* g1  = (const float*)d_in[26];
    const float* be1 = (const float*)d_in[27];
    const float* g2  = (const float*)d_in[28];
    const float* be2 = (const float*)d_in[29];

    float *SRC, *QKVp, *PROJ, *BQKV;
    __nv_bfloat16 *XH, *XL, *FFH, *FFL, *WqkvH, *WqkvL, *WoH, *WoL, *W1H, *W1L, *W2H, *W2L;
    cudaGetSymbolAddress((void**)&SRC,   g_SRC);
    cudaGetSymbolAddress((void**)&QKVp,  g_QKV);
    cudaGetSymbolAddress((void**)&PROJ,  g_PROJ);
    cudaGetSymbolAddress((void**)&XH,    g_XH);
    cudaGetSymbolAddress((void**)&XL,    g_XL);
    cudaGetSymbolAddress((void**)&FFH,   g_FFH);
    cudaGetSymbolAddress((void**)&FFL,   g_FFL);
    cudaGetSymbolAddress((void**)&WqkvH, g_WqkvH);
    cudaGetSymbolAddress((void**)&WqkvL, g_WqkvL);
    cudaGetSymbolAddress((void**)&WoH,   g_WoH);
    cudaGetSymbolAddress((void**)&WoL,   g_WoL);
    cudaGetSymbolAddress((void**)&W1H,   g_W1H);
    cudaGetSymbolAddress((void**)&W1L,   g_W1L);
    cudaGetSymbolAddress((void**)&W2H,   g_W2H);
    cudaGetSymbolAddress((void**)&W2L,   g_W2L);
    cudaGetSymbolAddress((void**)&BQKV,  g_bqkv);

    // raise dynamic smem limit for the pipelined GEMM (idempotent host-side calls)
    cudaFuncSetAttribute(gemm_kernel<false,false>, cudaFuncAttributeMaxDynamicSharedMemorySize, GSMEM);
    cudaFuncSetAttribute(gemm_kernel<true,true>,   cudaFuncAttributeMaxDynamicSharedMemorySize, GSMEM);

    build_src_kernel<<<1024, 256>>>(hand_t, head_t, hand_m1, head_m1,
                                    state_t, state_m1, tok_m1, tok_t);
    build_coord_kernel<<<98, 256>>>(c_hand_t, c_head_t, c_hand_m1, c_head_m1, tr_t, tr_m1);

    // split / pack all weights once
    split_qkv_w_kernel<<<2048, 256>>>(Wq, Wk, Wv);
    pack_qkv_b_kernel<<<(LL*QKVN + 255)/256, 256>>>(bq, bk, bv);
    split_kernel<<<2048, 256>>>(Wo, WoH, WoL, LL*DD*DD);
    split_kernel<<<2048, 256>>>(W1, W1H, W1L, LL*FFD*DD);
    split_kernel<<<2048, 256>>>(W2, W2H, W2L, LL*DD*FFD);

    // initial activation split
    split_kernel<<<2048, 256>>>(SRC, XH, XL, MM*DD);

    const int MB = (MM + 127)/128;   // 65
    for (int l = 0; l < LL; l++) {
        gemm_kernel<false,false><<<dim3(MB, QKVN/128), 256, GSMEM>>>(MM, QKVN, DD, XH, XL,
            WqkvH + (size_t)l*QKVN*DD, WqkvL + (size_t)l*QKVN*DD, BQKV + l*QKVN, QKVp, nullptr, nullptr);
        rope_split_kernel<<<(64*SS + 255)/256, 256>>>();
        attn_mma_kernel<<<dim3(17, 64), 128>>>(XH, XL);
        gemm_kernel<false,false><<<dim3(MB, DD/128), 256, GSMEM>>>(MM, DD, DD, XH, XL,
            WoH + (size_t)l*DD*DD, WoL + (size_t)l*DD*DD, bo + l*DD, PROJ, nullptr, nullptr);
        add_ln_kernel<<<MM, 128>>>(SRC, PROJ, g1 + l*DD, be1 + l*DD, XH, XL);
        gemm_kernel<true,true><<<dim3(MB, FFD/128), 256, GSMEM>>>(MM, FFD, DD, XH, XL,
            W1H + (size_t)l*FFD*DD, W1L + (size_t)l*FFD*DD, b1 + l*FFD, nullptr, FFH, FFL);
        gemm_kernel<false,false><<<dim3(MB, DD/128), 256, GSMEM>>>(MM, DD, FFD, FFH, FFL,
            W2H + (size_t)l*DD*FFD, W2L + (size_t)l*DD*FFD, b2 + l*DD, PROJ, nullptr, nullptr);
        add_ln_kernel<<<MM, 128>>>(SRC, PROJ, g2 + l*DD, be2 + l*DD, XH, XL);
    }
    copy_out_kernel<<<48, 256>>>((float*)d_out);
}